// round 1
// baseline (speedup 1.0000x reference)
#include <cuda_runtime.h>

static constexpr int Bn = 4096;
static constexpr int Dn = 512;
static constexpr int Hn = 16;

// Scratch (device globals: no allocation allowed in kernel_launch)
__device__ float g_A1[Dn * Dn];        // Wk @ M_flat
__device__ float g_A2[Dn * Dn];        // (Wk @ M_flat) @ Wo / H
__device__ float g_S[Dn * Dn];         // (lam ⊙ zs)^T @ zv
__device__ float g_T[Hn * Dn * Dn];    // partial-sum buffer / per-head T_h
__device__ float g_lam[Bn];
__device__ float g_cnt;

// ---------------------------------------------------------------------------
// lam_m[b] = clip(1-conf,0,1) * (lam > 0.3);  g_cnt = sum(mask)
// Single block, fixed reduction order -> deterministic.
// ---------------------------------------------------------------------------
__global__ void prep_lam_kernel(const float* __restrict__ conf) {
    int t = threadIdx.x;
    float local = 0.f;
    for (int i = t; i < Bn; i += 256) {
        float lam = 1.0f - conf[i];
        lam = fminf(fmaxf(lam, 0.f), 1.f);
        float m = (lam > 0.3f) ? 1.f : 0.f;
        g_lam[i] = lam * m;
        local += m;
    }
#pragma unroll
    for (int o = 16; o > 0; o >>= 1)
        local += __shfl_down_sync(0xffffffffu, local, o);
    __shared__ float ws[8];
    if ((t & 31) == 0) ws[t >> 5] = local;
    __syncthreads();
    if (t == 0) {
        float s = 0.f;
#pragma unroll
        for (int w = 0; w < 8; w++) s += ws[w];
        g_cnt = s;  // exact: sum of 0/1 floats
    }
}

// Deterministic reduction of K-split partials.
__global__ void reduce_partials(const float* __restrict__ part, float* __restrict__ dst,
                                int nElem, int nPart) {
    int i = blockIdx.x * blockDim.x + threadIdx.x;
    if (i < nElem) {
        float s = 0.f;
        for (int p = 0; p < nPart; p++) s += part[(long)p * nElem + i];
        dst[i] = s;
    }
}

// ---------------------------------------------------------------------------
// 64x64x16-tile fp32 GEMM, 256 threads, 4x4 microtile.
//   TA:     A is K-major (A[k*lda + m]), else row-major (A[m*lda + k])
//   KSCALE: multiply A-tile rows by kscale[k] while loading
//   EPI 0:  C = alpha * acc   (with optional split offset for partials)
//   EPI 2:  C = addC + acc / (g_cnt + 1e-6)
// All dims used are multiples of 64 / 16 -> no bounds checks.
// Batch over blockIdx.z: batch = z/ksplit (ptr strides sA/sB/sC/sAdd),
// split = z%ksplit (K range + sSplit offset into partial buffer).
// ---------------------------------------------------------------------------
template <int TA, int KSCALE, int EPI>
__global__ __launch_bounds__(256) void gemm64(
    const float* __restrict__ A, const float* __restrict__ B,
    float* __restrict__ C, const float* __restrict__ addC,
    int K, int lda, int ldb, int ldc,
    int ksplit, long sA, long sB, long sC, long sAdd, long sSplit,
    float alpha, const float* __restrict__ kscale) {
    int bz = blockIdx.z;
    int batch = bz / ksplit;
    int split = bz - batch * ksplit;
    A += (long)batch * sA;
    B += (long)batch * sB;
    C += (long)batch * sC + (long)split * sSplit;
    int kChunk = K / ksplit;
    int k0 = split * kChunk;
    int k1 = k0 + kChunk;

    __shared__ float As[16][68];
    __shared__ float Bs[16][68];

    int tid = threadIdx.x;
    int tx = tid & 15, ty = tid >> 4;
    int rowBase = blockIdx.y * 64, colBase = blockIdx.x * 64;

    float acc[4][4] = {};

    for (int k = k0; k < k1; k += 16) {
        if (TA) {
            int m4 = (tid & 15) * 4;
            int kk = tid >> 4;
            float4 v = *reinterpret_cast<const float4*>(
                &A[(long)(k + kk) * lda + rowBase + m4]);
            if (KSCALE) {
                float s = kscale[k + kk];
                v.x *= s; v.y *= s; v.z *= s; v.w *= s;
            }
            *reinterpret_cast<float4*>(&As[kk][m4]) = v;
        } else {
            int m = tid >> 2;
            int kk4 = (tid & 3) * 4;
            float4 v = *reinterpret_cast<const float4*>(
                &A[(long)(rowBase + m) * lda + k + kk4]);
            As[kk4 + 0][m] = v.x;
            As[kk4 + 1][m] = v.y;
            As[kk4 + 2][m] = v.z;
            As[kk4 + 3][m] = v.w;
        }
        {
            int n4 = (tid & 15) * 4;
            int kk = tid >> 4;
            float4 v = *reinterpret_cast<const float4*>(
                &B[(long)(k + kk) * ldb + colBase + n4]);
            *reinterpret_cast<float4*>(&Bs[kk][n4]) = v;
        }
        __syncthreads();
#pragma unroll
        for (int kk = 0; kk < 16; kk++) {
            float4 a = *reinterpret_cast<const float4*>(&As[kk][ty * 4]);
            float4 b = *reinterpret_cast<const float4*>(&Bs[kk][tx * 4]);
            float ra[4] = {a.x, a.y, a.z, a.w};
            float rb[4] = {b.x, b.y, b.z, b.w};
#pragma unroll
            for (int i = 0; i < 4; i++)
#pragma unroll
                for (int j = 0; j < 4; j++) acc[i][j] += ra[i] * rb[j];
        }
        __syncthreads();
    }

    float scale = (EPI == 2) ? (1.f / (g_cnt + 1e-6f)) : alpha;
    if (EPI == 2) addC += (long)batch * sAdd;
#pragma unroll
    for (int i = 0; i < 4; i++) {
        int r = rowBase + ty * 4 + i;
#pragma unroll
        for (int j = 0; j < 4; j++) {
            int c = colBase + tx * 4 + j;
            long idx = (long)r * ldc + c;
            float v = acc[i][j] * scale;
            if (EPI == 2)
                C[idx] = addC[idx] + v;
            else
                C[idx] = v;
        }
    }
}

extern "C" void kernel_launch(void* const* d_in, const int* in_sizes, int n_in,
                              void* d_out, int out_size) {
    const float* zq = (const float*)d_in[0];
    const float* zs = (const float*)d_in[1];
    const float* zv = (const float*)d_in[2];
    const float* cf = (const float*)d_in[3];
    const float* Wk = (const float*)d_in[4];
    const float* Wv = (const float*)d_in[5];
    const float* Wo = (const float*)d_in[6];
    const float* mem = (const float*)d_in[7];

    float* out = (float*)d_out;
    float* vret = out;                         // (B, D)
    float* newmem = out + (long)Bn * Dn;       // (H, D, D)

    float *pA1, *pA2, *pS, *pT, *pLam;
    cudaGetSymbolAddress((void**)&pA1, g_A1);
    cudaGetSymbolAddress((void**)&pA2, g_A2);
    cudaGetSymbolAddress((void**)&pS, g_S);
    cudaGetSymbolAddress((void**)&pT, g_T);
    cudaGetSymbolAddress((void**)&pLam, g_lam);

    const long DD = (long)Dn * Dn;

    // lam mask + count
    prep_lam_kernel<<<1, 256>>>(cf);

    // 1) A1 = Wk(512x8192) @ M_flat(8192x512)   [16-way K-split partials in g_T]
    gemm64<0, 0, 0><<<dim3(8, 8, 16), 256>>>(Wk, mem, pT, nullptr,
        /*K*/ 8192, /*lda*/ 8192, /*ldb*/ 512, /*ldc*/ 512,
        /*ksplit*/ 16, 0, 0, 0, 0, /*sSplit*/ DD, 1.f, nullptr);
    reduce_partials<<<(Dn * Dn + 255) / 256, 256>>>(pT, pA1, Dn * Dn, 16);

    // 2) A2 = A1 @ Wo * (1/H)
    gemm64<0, 0, 0><<<dim3(8, 8, 1), 256>>>(pA1, Wo, pA2, nullptr,
        512, 512, 512, 512, 1, 0, 0, 0, 0, 0, 1.f / Hn, nullptr);

    // 3) v_ret = zq @ A2
    gemm64<0, 0, 0><<<dim3(8, 64, 1), 256>>>(zq, pA2, vret, nullptr,
        512, 512, 512, 512, 1, 0, 0, 0, 0, 0, 1.f, nullptr);

    // 4) S = (lam ⊙ zs)^T @ zv     [8-way K-split partials in g_T]
    gemm64<1, 1, 0><<<dim3(8, 8, 8), 256>>>(zs, zv, pT, nullptr,
        /*K*/ 4096, /*lda*/ 512, /*ldb*/ 512, /*ldc*/ 512,
        /*ksplit*/ 8, 0, 0, 0, 0, /*sSplit*/ DD, 1.f, pLam);
    reduce_partials<<<(Dn * Dn + 255) / 256, 256>>>(pT, pS, Dn * Dn, 8);

    // 5) T_h = Wk_h^T @ S          (batched over h via blockIdx.z)
    gemm64<1, 0, 0><<<dim3(8, 8, 16), 256>>>(Wk, pS, pT, nullptr,
        512, /*lda*/ 8192, /*ldb*/ 512, /*ldc*/ 512,
        1, /*sA*/ 512, /*sB*/ 0, /*sC*/ DD, 0, 0, 1.f, nullptr);

    // 6) new_mem_h = mem_h + (T_h @ Wv_h) / (cnt + 1e-6)
    gemm64<0, 0, 2><<<dim3(8, 8, 16), 256>>>(pT, Wv, newmem, mem,
        512, /*lda*/ 512, /*ldb*/ 8192, /*ldc*/ 512,
        1, /*sA*/ DD, /*sB*/ 512, /*sC*/ DD, /*sAdd*/ DD, 0, 1.f, nullptr);
}

// round 4
// speedup vs baseline: 1.6570x; 1.6570x over previous
#include <cuda_runtime.h>
#include <cuda_bf16.h>
#include <cstdint>

static constexpr int Bn = 4096;
static constexpr int Dn = 512;
static constexpr int Hn = 16;
static constexpr long DD = (long)Dn * Dn;

// ---------------------------------------------------------------------------
// Device scratch (no allocations allowed in kernel_launch)
// ---------------------------------------------------------------------------
__device__ float g_A1[Dn * Dn];
__device__ float g_A2[Dn * Dn];
__device__ float g_S[Dn * Dn];
__device__ float g_T[Hn * Dn * Dn];
__device__ float g_lam[Bn];
__device__ float g_cnt;

#define BF16_SCRATCH(name, n) __device__ __align__(16) __nv_bfloat16 name[n]
BF16_SCRATCH(sWk_h, 512 * 8192);  BF16_SCRATCH(sWk_l, 512 * 8192);
BF16_SCRATCH(sWkT_h, 8192 * 512); BF16_SCRATCH(sWkT_l, 8192 * 512);
BF16_SCRATCH(sMemT_h, 512 * 8192);BF16_SCRATCH(sMemT_l, 512 * 8192);
BF16_SCRATCH(sWvT_h, 8192 * 512); BF16_SCRATCH(sWvT_l, 8192 * 512);
BF16_SCRATCH(sWoT_h, 512 * 512);  BF16_SCRATCH(sWoT_l, 512 * 512);
BF16_SCRATCH(sZq_h, 4096 * 512);  BF16_SCRATCH(sZq_l, 4096 * 512);
BF16_SCRATCH(sZsT_h, 512 * 4096); BF16_SCRATCH(sZsT_l, 512 * 4096);
BF16_SCRATCH(sZvT_h, 512 * 4096); BF16_SCRATCH(sZvT_l, 512 * 4096);
BF16_SCRATCH(sA1_h, 512 * 512);   BF16_SCRATCH(sA1_l, 512 * 512);
BF16_SCRATCH(sA2T_h, 512 * 512);  BF16_SCRATCH(sA2T_l, 512 * 512);
BF16_SCRATCH(sST_h, 512 * 512);   BF16_SCRATCH(sST_l, 512 * 512);
BF16_SCRATCH(sT_h, 16 * 512 * 512); BF16_SCRATCH(sT_l, 16 * 512 * 512);

// ---------------------------------------------------------------------------
// small helpers
// ---------------------------------------------------------------------------
__device__ __forceinline__ uint32_t smem_u32(const void* p) {
    uint32_t a;
    asm("{ .reg .u64 t; cvta.to.shared.u64 t, %1; cvt.u32.u64 %0, t; }"
        : "=r"(a) : "l"(p));
    return a;
}
__device__ __forceinline__ void ldsm4(uint32_t* r, uint32_t addr) {
    asm volatile("ldmatrix.sync.aligned.m8n8.x4.shared.b16 {%0,%1,%2,%3}, [%4];"
                 : "=r"(r[0]), "=r"(r[1]), "=r"(r[2]), "=r"(r[3]) : "r"(addr));
}
__device__ __forceinline__ void mma16816(float* c, const uint32_t* a, const uint32_t* b) {
    asm volatile(
        "mma.sync.aligned.m16n8k16.row.col.f32.bf16.bf16.f32 "
        "{%0,%1,%2,%3}, {%4,%5,%6,%7}, {%8,%9}, {%0,%1,%2,%3};"
        : "+f"(c[0]), "+f"(c[1]), "+f"(c[2]), "+f"(c[3])
        : "r"(a[0]), "r"(a[1]), "r"(a[2]), "r"(a[3]), "r"(b[0]), "r"(b[1]));
}
__device__ __forceinline__ void cp16(uint32_t dst, const void* src) {
    asm volatile("cp.async.cg.shared.global [%0], [%1], 16;" :: "r"(dst), "l"(src));
}
__device__ __forceinline__ void cp_commit() {
    asm volatile("cp.async.commit_group;");
}
__device__ __forceinline__ void cp_wait1() {
    asm volatile("cp.async.wait_group 1;");
}
__device__ __forceinline__ void cp_wait0() {
    asm volatile("cp.async.wait_group 0;");
}

// ---------------------------------------------------------------------------
// lam prep (deterministic)
// ---------------------------------------------------------------------------
__global__ void prep_lam_kernel(const float* __restrict__ conf) {
    int t = threadIdx.x;
    float local = 0.f;
    for (int i = t; i < Bn; i += 256) {
        float lam = fminf(fmaxf(1.0f - conf[i], 0.f), 1.f);
        float m = (lam > 0.3f) ? 1.f : 0.f;
        g_lam[i] = lam * m;
        local += m;
    }
#pragma unroll
    for (int o = 16; o > 0; o >>= 1) local += __shfl_down_sync(0xffffffffu, local, o);
    __shared__ float ws[8];
    if ((t & 31) == 0) ws[t >> 5] = local;
    __syncthreads();
    if (t == 0) {
        float s = 0.f;
#pragma unroll
        for (int w = 0; w < 8; w++) s += ws[w];
        g_cnt = s;
    }
}

__global__ void reduce_partials(const float* __restrict__ part, float* __restrict__ dst,
                                int nElem, int nPart) {
    int i = blockIdx.x * blockDim.x + threadIdx.x;
    if (i < nElem) {
        float s = 0.f;
        for (int p = 0; p < nPart; p++) s += part[(long)p * nElem + i];
        dst[i] = s;
    }
}

// fp32 -> bf16 hi/lo split
__global__ void splitK(const float* __restrict__ src, __nv_bfloat16* __restrict__ hi,
                       __nv_bfloat16* __restrict__ lo, long n) {
    long i = 2 * ((long)blockIdx.x * blockDim.x + threadIdx.x);
    if (i < n) {
        float2 x = *(const float2*)(src + i);
        __nv_bfloat16 h0 = __float2bfloat16(x.x), h1 = __float2bfloat16(x.y);
        __nv_bfloat162 hv{h0, h1};
        __nv_bfloat162 lv{__float2bfloat16(x.x - __bfloat162float(h0)),
                          __float2bfloat16(x.y - __bfloat162float(h1))};
        *(__nv_bfloat162*)(hi + i) = hv;
        *(__nv_bfloat162*)(lo + i) = lv;
    }
}

// fp32 [R,C] -> transposed bf16 hi/lo [C,R], optional per-src-row scale
template <int SCALE>
__global__ void splitT(const float* __restrict__ src, __nv_bfloat16* __restrict__ hi,
                       __nv_bfloat16* __restrict__ lo, int R, int C,
                       const float* __restrict__ rs) {
    __shared__ float t[32][33];
    int c0 = blockIdx.x * 32, r0 = blockIdx.y * 32;
    int tx = threadIdx.x, ty = threadIdx.y;  // 32x8
#pragma unroll
    for (int i = 0; i < 32; i += 8) {
        float v = src[(long)(r0 + ty + i) * C + c0 + tx];
        if (SCALE) v *= rs[r0 + ty + i];
        t[ty + i][tx] = v;
    }
    __syncthreads();
#pragma unroll
    for (int i = 0; i < 32; i += 8) {
        float v = t[tx][ty + i];
        long o = (long)(c0 + ty + i) * R + r0 + tx;
        __nv_bfloat16 h = __float2bfloat16(v);
        hi[o] = h;
        lo[o] = __float2bfloat16(v - __bfloat162float(h));
    }
}

// ---------------------------------------------------------------------------
// HMMA bf16-split GEMM.
// C[128x128 tile] = sum of 3 passes (AhBh, AhBl, AlBh), fp32 accumulators.
// A: [M,K] bf16 row-major (K contiguous); B: [N,K] bf16 (= B^T, K contiguous).
// EPI 0: C = alpha * acc (K-split partial offset supported)
// EPI 2: C = addC + acc / (g_cnt + 1e-6)
// 256 threads = 8 warps (4 warpM x 2 warpN), warp tile 32x64.
// Smem rows padded to 80B (stride-80 -> conflict-free ldmatrix).
// ---------------------------------------------------------------------------
template <int EPI>
__global__ __launch_bounds__(256) void mma_gemm(
    const __nv_bfloat16* __restrict__ Ah, const __nv_bfloat16* __restrict__ Al,
    const __nv_bfloat16* __restrict__ Bh, const __nv_bfloat16* __restrict__ Bl,
    float* __restrict__ C, const float* __restrict__ addC,
    int K, int ldA, int ldB, int ldC,
    int ksplit, long sA, long sB, long sC, long sAdd, long sSplit, float alpha) {
    __shared__ __align__(16) char sm[2 * 20480];  // 2 bufs x (A 10240 + B 10240)
    const uint32_t sbase = smem_u32(sm);
    const int tid = threadIdx.x;
    const int wid = tid >> 5, lane = tid & 31;
    const int warpM = wid & 3, warpN = wid >> 2;

    int bz = blockIdx.z;
    int batch = bz / ksplit;
    int split = bz - batch * ksplit;
    Ah += (long)batch * sA; Al += (long)batch * sA;
    Bh += (long)batch * sB; Bl += (long)batch * sB;
    C += (long)batch * sC + (long)split * sSplit;
    const int kLen = K / ksplit;
    const long k0 = (long)split * kLen;
    const int rowA = blockIdx.y * 128;
    const int colB = blockIdx.x * 128;

    const int nCk = kLen >> 5;       // chunks of K=32
    const int nTot = 3 * nCk;

    // per-thread load indices: 2 x (row, 16B-chunk) for A and B each
    const int lr = tid >> 2;         // 0..63
    const int lc = tid & 3;          // 0..3

    float acc[2][8][4] = {};

    // ldmatrix lane-address components
    const uint32_t aAddrOff = (uint32_t)(warpM * 32 + (lane & 15)) * 80 + (lane >> 4) * 16;
    const uint32_t bAddrOff = (uint32_t)(warpN * 64 + ((lane >> 4) << 3) + (lane & 7)) * 80 +
                              ((lane >> 3) & 1) * 16;

    auto issue_load = [&](int c, int buf) {
        const int pass = c / nCk;
        const int ck = c - pass * nCk;
        const __nv_bfloat16* Ap = (pass == 2) ? Al : Ah;
        const __nv_bfloat16* Bp = (pass == 1) ? Bl : Bh;
        const long kb = k0 + (long)ck * 32;
        uint32_t aT = sbase + buf * 20480;
        uint32_t bT = aT + 10240;
#pragma unroll
        for (int i = 0; i < 2; i++) {
            int r = lr + i * 64;
            uint32_t so = (uint32_t)r * 80 + lc * 16;
            cp16(aT + so, Ap + (long)(rowA + r) * ldA + kb + lc * 8);
            cp16(bT + so, Bp + (long)(colB + r) * ldB + kb + lc * 8);
        }
    };

    issue_load(0, 0);
    cp_commit();

    for (int c = 0; c < nTot; c++) {
        const int buf = c & 1;
        if (c + 1 < nTot) {
            issue_load(c + 1, (c + 1) & 1);
            cp_commit();
            cp_wait1();
        } else {
            cp_wait0();
        }
        __syncthreads();

        uint32_t aT = sbase + buf * 20480;
        uint32_t bT = aT + 10240;
#pragma unroll
        for (int ks = 0; ks < 2; ks++) {
            uint32_t af[2][4];
#pragma unroll
            for (int mt = 0; mt < 2; mt++)
                ldsm4(af[mt], aT + aAddrOff + mt * (16 * 80) + ks * 32);
            uint32_t bf[8][2];
#pragma unroll
            for (int q = 0; q < 4; q++) {
                uint32_t r4[4];
                ldsm4(r4, bT + bAddrOff + q * (16 * 80) + ks * 32);
                bf[2 * q][0] = r4[0]; bf[2 * q][1] = r4[1];
                bf[2 * q + 1][0] = r4[2]; bf[2 * q + 1][1] = r4[3];
            }
#pragma unroll
            for (int mt = 0; mt < 2; mt++)
#pragma unroll
                for (int nt = 0; nt < 8; nt++)
                    mma16816(acc[mt][nt], af[mt], bf[nt]);
        }
        __syncthreads();
    }

    // epilogue
    float scale = (EPI == 2) ? (1.f / (g_cnt + 1e-6f)) : alpha;
    const float* addP = (EPI == 2) ? (addC + (long)batch * sAdd) : nullptr;
#pragma unroll
    for (int mt = 0; mt < 2; mt++) {
        int mrow = rowA + warpM * 32 + mt * 16 + (lane >> 2);
#pragma unroll
        for (int nt = 0; nt < 8; nt++) {
            int ncol = colB + warpN * 64 + nt * 8 + 2 * (lane & 3);
            long i0 = (long)mrow * ldC + ncol;
            long i1 = (long)(mrow + 8) * ldC + ncol;
            float2 v0{acc[mt][nt][0] * scale, acc[mt][nt][1] * scale};
            float2 v1{acc[mt][nt][2] * scale, acc[mt][nt][3] * scale};
            if (EPI == 2) {
                v0.x += addP[i0]; v0.y += addP[i0 + 1];
                v1.x += addP[i1]; v1.y += addP[i1 + 1];
            }
            *(float2*)(C + i0) = v0;
            *(float2*)(C + i1) = v1;
        }
    }
}

// ---------------------------------------------------------------------------
extern "C" void kernel_launch(void* const* d_in, const int* in_sizes, int n_in,
                              void* d_out, int out_size) {
    const float* zq = (const float*)d_in[0];
    const float* zs = (const float*)d_in[1];
    const float* zv = (const float*)d_in[2];
    const float* cf = (const float*)d_in[3];
    const float* Wk = (const float*)d_in[4];
    const float* Wv = (const float*)d_in[5];
    const float* Wo = (const float*)d_in[6];
    const float* mem = (const float*)d_in[7];

    float* out = (float*)d_out;
    float* vret = out;
    float* newmem = out + (long)Bn * Dn;

    float *pA1, *pA2, *pS, *pT, *pLam;
    cudaGetSymbolAddress((void**)&pA1, g_A1);
    cudaGetSymbolAddress((void**)&pA2, g_A2);
    cudaGetSymbolAddress((void**)&pS, g_S);
    cudaGetSymbolAddress((void**)&pT, g_T);
    cudaGetSymbolAddress((void**)&pLam, g_lam);

#define SYM(p, s) __nv_bfloat16* p; cudaGetSymbolAddress((void**)&p, s)
    SYM(pWk_h, sWk_h);   SYM(pWk_l, sWk_l);
    SYM(pWkT_h, sWkT_h); SYM(pWkT_l, sWkT_l);
    SYM(pMemT_h, sMemT_h); SYM(pMemT_l, sMemT_l);
    SYM(pWvT_h, sWvT_h); SYM(pWvT_l, sWvT_l);
    SYM(pWoT_h, sWoT_h); SYM(pWoT_l, sWoT_l);
    SYM(pZq_h, sZq_h);   SYM(pZq_l, sZq_l);
    SYM(pZsT_h, sZsT_h); SYM(pZsT_l, sZsT_l);
    SYM(pZvT_h, sZvT_h); SYM(pZvT_l, sZvT_l);
    SYM(pA1_h, sA1_h);   SYM(pA1_l, sA1_l);
    SYM(pA2T_h, sA2T_h); SYM(pA2T_l, sA2T_l);
    SYM(pST_h, sST_h);   SYM(pST_l, sST_l);
    SYM(pT_h, sT_h);     SYM(pT_l, sT_l);
#undef SYM

    dim3 tb(32, 8);

    prep_lam_kernel<<<1, 256>>>(cf);

    // conversions
    splitK<<<(512L * 8192 / 2 + 255) / 256, 256>>>(Wk, pWk_h, pWk_l, 512L * 8192);
    splitT<0><<<dim3(256, 16), tb>>>(Wk, pWkT_h, pWkT_l, 512, 8192, nullptr);
    splitT<0><<<dim3(16, 256), tb>>>(mem, pMemT_h, pMemT_l, 8192, 512, nullptr);
    splitT<0><<<dim3(256, 16), tb>>>(Wv, pWvT_h, pWvT_l, 512, 8192, nullptr);
    splitT<0><<<dim3(16, 16), tb>>>(Wo, pWoT_h, pWoT_l, 512, 512, nullptr);
    splitK<<<(4096L * 512 / 2 + 255) / 256, 256>>>(zq, pZq_h, pZq_l, 4096L * 512);
    splitT<1><<<dim3(16, 128), tb>>>(zs, pZsT_h, pZsT_l, 4096, 512, pLam);
    splitT<0><<<dim3(16, 128), tb>>>(zv, pZvT_h, pZvT_l, 4096, 512, nullptr);

    // 1) A1 = Wk @ mem_flat   (K=8192, 16-way K-split)
    mma_gemm<0><<<dim3(4, 4, 16), 256>>>(pWk_h, pWk_l, pMemT_h, pMemT_l,
        pT, nullptr, 8192, 8192, 8192, 512, 16, 0, 0, 0, 0, DD, 1.f);
    reduce_partials<<<(Dn * Dn + 255) / 256, 256>>>(pT, pA1, Dn * Dn, 16);
    splitK<<<(DD / 2 + 255) / 256, 256>>>(pA1, pA1_h, pA1_l, DD);

    // 2) A2 = (A1 @ Wo) / H   (4-way K-split)
    mma_gemm<0><<<dim3(4, 4, 4), 256>>>(pA1_h, pA1_l, pWoT_h, pWoT_l,
        pT, nullptr, 512, 512, 512, 512, 4, 0, 0, 0, 0, DD, 1.f / Hn);
    reduce_partials<<<(Dn * Dn + 255) / 256, 256>>>(pT, pA2, Dn * Dn, 4);
    splitT<0><<<dim3(16, 16), tb>>>(pA2, pA2T_h, pA2T_l, 512, 512, nullptr);

    // 3) v_ret = zq @ A2
    mma_gemm<0><<<dim3(4, 32, 1), 256>>>(pZq_h, pZq_l, pA2T_h, pA2T_l,
        vret, nullptr, 512, 512, 512, 512, 1, 0, 0, 0, 0, 0, 1.f);

    // 4) S = zs^T diag(lam_m) zv   (K=4096, 8-way K-split)
    mma_gemm<0><<<dim3(4, 4, 8), 256>>>(pZsT_h, pZsT_l, pZvT_h, pZvT_l,
        pT, nullptr, 4096, 4096, 4096, 512, 8, 0, 0, 0, 0, DD, 1.f);
    reduce_partials<<<(Dn * Dn + 255) / 256, 256>>>(pT, pS, Dn * Dn, 8);
    splitT<0><<<dim3(16, 16), tb>>>(pS, pST_h, pST_l, 512, 512, nullptr);

    // 5) T_h = Wk_h^T @ S   (batched over 16 heads)
    mma_gemm<0><<<dim3(4, 4, 16), 256>>>(pWkT_h, pWkT_l, pST_h, pST_l,
        pT, nullptr, 512, 512, 512, 512, 1, DD, 0, DD, 0, 0, 1.f);
    splitK<<<(16L * DD / 2 + 255) / 256, 256>>>(pT, pT_h, pT_l, 16L * DD);

    // 6) new_mem_h = mem_h + (T_h @ Wv_h) / (cnt + 1e-6)
    mma_gemm<2><<<dim3(4, 4, 16), 256>>>(pT_h, pT_l, pWvT_h, pWvT_l,
        newmem, mem, 512, 512, 512, 512, 1, DD, DD, DD, DD, 0, 1.f);
}

// round 6
// speedup vs baseline: 2.0087x; 1.2122x over previous
#include <cuda_runtime.h>
#include <cuda_bf16.h>
#include <cstdint>

static constexpr int Bn = 4096;
static constexpr int Dn = 512;
static constexpr int Hn = 16;
static constexpr long DD = (long)Dn * Dn;

// ---------------------------------------------------------------------------
// Device scratch
// ---------------------------------------------------------------------------
__device__ float g_A1[Dn * Dn];
__device__ float g_A2[Dn * Dn];
__device__ float g_S[Dn * Dn];
__device__ float g_T[Hn * Dn * Dn];     // fp32 K-split partials
__device__ float g_lam[Bn];
__device__ float g_cnt;

#define BF16_SCRATCH(name, n) __device__ __align__(16) __nv_bfloat16 name[n]
BF16_SCRATCH(sWk_h, 512 * 8192);  BF16_SCRATCH(sWk_l, 512 * 8192);
BF16_SCRATCH(sWkT_h, 8192 * 512); BF16_SCRATCH(sWkT_l, 8192 * 512);
BF16_SCRATCH(sMemT_h, 512 * 8192);BF16_SCRATCH(sMemT_l, 512 * 8192);
BF16_SCRATCH(sWvT_h, 8192 * 512); BF16_SCRATCH(sWvT_l, 8192 * 512);
BF16_SCRATCH(sWoT_h, 512 * 512);  BF16_SCRATCH(sWoT_l, 512 * 512);
BF16_SCRATCH(sZq_h, 4096 * 512);  BF16_SCRATCH(sZq_l, 4096 * 512);
BF16_SCRATCH(sZsT_h, 512 * 4096); BF16_SCRATCH(sZsT_l, 512 * 4096);
BF16_SCRATCH(sZvT_h, 512 * 4096); BF16_SCRATCH(sZvT_l, 512 * 4096);
BF16_SCRATCH(sA1_h, 512 * 512);   BF16_SCRATCH(sA1_l, 512 * 512);
BF16_SCRATCH(sA2T_h, 512 * 512);  BF16_SCRATCH(sA2T_l, 512 * 512);
BF16_SCRATCH(sST_h, 512 * 512);   BF16_SCRATCH(sST_l, 512 * 512);
BF16_SCRATCH(sT_h, 16 * 512 * 512); BF16_SCRATCH(sT_l, 16 * 512 * 512);

// ---------------------------------------------------------------------------
// helpers
// ---------------------------------------------------------------------------
__device__ __forceinline__ uint32_t smem_u32(const void* p) {
    uint32_t a;
    asm("{ .reg .u64 t; cvta.to.shared.u64 t, %1; cvt.u32.u64 %0, t; }"
        : "=r"(a) : "l"(p));
    return a;
}
__device__ __forceinline__ void ldsm4(uint32_t* r, uint32_t addr) {
    asm volatile("ldmatrix.sync.aligned.m8n8.x4.shared.b16 {%0,%1,%2,%3}, [%4];"
                 : "=r"(r[0]), "=r"(r[1]), "=r"(r[2]), "=r"(r[3]) : "r"(addr));
}
__device__ __forceinline__ void mma16816(float* c, const uint32_t* a, const uint32_t* b) {
    asm volatile(
        "mma.sync.aligned.m16n8k16.row.col.f32.bf16.bf16.f32 "
        "{%0,%1,%2,%3}, {%4,%5,%6,%7}, {%8,%9}, {%0,%1,%2,%3};"
        : "+f"(c[0]), "+f"(c[1]), "+f"(c[2]), "+f"(c[3])
        : "r"(a[0]), "r"(a[1]), "r"(a[2]), "r"(a[3]), "r"(b[0]), "r"(b[1]));
}
__device__ __forceinline__ void cp16(uint32_t dst, const void* src) {
    asm volatile("cp.async.cg.shared.global [%0], [%1], 16;" :: "r"(dst), "l"(src));
}
__device__ __forceinline__ void cp_commit() { asm volatile("cp.async.commit_group;"); }
__device__ __forceinline__ void cp_wait1() { asm volatile("cp.async.wait_group 1;"); }
__device__ __forceinline__ void cp_wait0() { asm volatile("cp.async.wait_group 0;"); }

__device__ __forceinline__ void split1(float v, __nv_bfloat16& h, __nv_bfloat16& l) {
    h = __float2bfloat16(v);
    l = __float2bfloat16(v - __bfloat162float(h));
}

// ---------------------------------------------------------------------------
// lam prep
// ---------------------------------------------------------------------------
__global__ void prep_lam_kernel(const float* __restrict__ conf) {
    int t = threadIdx.x;
    float local = 0.f;
    for (int i = t; i < Bn; i += 256) {
        float lam = fminf(fmaxf(1.0f - conf[i], 0.f), 1.f);
        float m = (lam > 0.3f) ? 1.f : 0.f;
        g_lam[i] = lam * m;
        local += m;
    }
#pragma unroll
    for (int o = 16; o > 0; o >>= 1) local += __shfl_down_sync(0xffffffffu, local, o);
    __shared__ float ws[8];
    if ((t & 31) == 0) ws[t >> 5] = local;
    __syncthreads();
    if (t == 0) {
        float s = 0.f;
#pragma unroll
        for (int w = 0; w < 8; w++) s += ws[w];
        g_cnt = s;
    }
}

__global__ void reduce_partials(const float* __restrict__ part, float* __restrict__ dst,
                                int nElem, int nPart) {
    int i = blockIdx.x * blockDim.x + threadIdx.x;
    if (i < nElem) {
        float s = 0.f;
        for (int p = 0; p < nPart; p++) s += part[(long)p * nElem + i];
        dst[i] = s;
    }
}

// fused: sum K-split partials then write bf16 hi/lo (no fp32 round-trip)
__global__ void reduce_split(const float* __restrict__ part, __nv_bfloat16* __restrict__ hi,
                             __nv_bfloat16* __restrict__ lo, int nElem, int nPart) {
    int i = blockIdx.x * blockDim.x + threadIdx.x;
    if (i < nElem) {
        float s = 0.f;
        for (int p = 0; p < nPart; p++) s += part[(long)p * nElem + i];
        __nv_bfloat16 h, l;
        split1(s, h, l);
        hi[i] = h; lo[i] = l;
    }
}

// fp32 [R,C] -> transposed bf16 hi/lo [C,R], optional per-src-row scale
template <int SCALE>
__global__ void splitT(const float* __restrict__ src, __nv_bfloat16* __restrict__ hi,
                       __nv_bfloat16* __restrict__ lo, int R, int C,
                       const float* __restrict__ rs) {
    __shared__ float t[32][33];
    int c0 = blockIdx.x * 32, r0 = blockIdx.y * 32;
    int tx = threadIdx.x, ty = threadIdx.y;  // 32x8
#pragma unroll
    for (int i = 0; i < 32; i += 8) {
        float v = src[(long)(r0 + ty + i) * C + c0 + tx];
        if (SCALE) v *= rs[r0 + ty + i];
        t[ty + i][tx] = v;
    }
    __syncthreads();
#pragma unroll
    for (int i = 0; i < 32; i += 8) {
        float v = t[tx][ty + i];
        long o = (long)(c0 + ty + i) * R + r0 + tx;
        __nv_bfloat16 h, l;
        split1(v, h, l);
        hi[o] = h; lo[o] = l;
    }
}

// Wk (512x8192): one read -> direct split + transposed split
__global__ void convWk(const float* __restrict__ src,
                       __nv_bfloat16* __restrict__ dh, __nv_bfloat16* __restrict__ dl,
                       __nv_bfloat16* __restrict__ th, __nv_bfloat16* __restrict__ tl) {
    __shared__ float t[32][33];
    const int R = 512, C = 8192;
    int c0 = blockIdx.x * 32, r0 = blockIdx.y * 32;
    int tx = threadIdx.x, ty = threadIdx.y;
#pragma unroll
    for (int i = 0; i < 32; i += 8) {
        long o = (long)(r0 + ty + i) * C + c0 + tx;
        float v = src[o];
        t[ty + i][tx] = v;
        __nv_bfloat16 h, l;
        split1(v, h, l);
        dh[o] = h; dl[o] = l;
    }
    __syncthreads();
#pragma unroll
    for (int i = 0; i < 32; i += 8) {
        float v = t[tx][ty + i];
        long o = (long)(c0 + ty + i) * R + r0 + tx;
        __nv_bfloat16 h, l;
        split1(v, h, l);
        th[o] = h; tl[o] = l;
    }
}

// zq (direct split) + zs (lam-scaled, transposed) + zv (transposed). 4096x512.
__global__ void convZ(const float* __restrict__ zq, const float* __restrict__ zs,
                      const float* __restrict__ zv,
                      __nv_bfloat16* __restrict__ qh, __nv_bfloat16* __restrict__ ql,
                      __nv_bfloat16* __restrict__ sh, __nv_bfloat16* __restrict__ sl,
                      __nv_bfloat16* __restrict__ vh, __nv_bfloat16* __restrict__ vl) {
    __shared__ float ts[32][33], tv[32][33];
    const int R = 4096, C = 512;
    int c0 = blockIdx.x * 32, r0 = blockIdx.y * 32;
    int tx = threadIdx.x, ty = threadIdx.y;
#pragma unroll
    for (int i = 0; i < 32; i += 8) {
        int r = r0 + ty + i;
        long o = (long)r * C + c0 + tx;
        float q = zq[o];
        __nv_bfloat16 h, l;
        split1(q, h, l);
        qh[o] = h; ql[o] = l;
        ts[ty + i][tx] = zs[o] * g_lam[r];
        tv[ty + i][tx] = zv[o];
    }
    __syncthreads();
#pragma unroll
    for (int i = 0; i < 32; i += 8) {
        long o = (long)(c0 + ty + i) * R + r0 + tx;
        __nv_bfloat16 h, l;
        split1(ts[tx][ty + i], h, l);
        sh[o] = h; sl[o] = l;
        split1(tv[tx][ty + i], h, l);
        vh[o] = h; vl[o] = l;
    }
}

// ---------------------------------------------------------------------------
// HMMA bf16-split GEMM, 128x128 tile, 8 warps (4x2), warp tile 32x64,
// K-chunk 64, 2-stage cp.async pipeline, smem rows stride 144B.
// EPI 0: C (fp32) = alpha*acc;  EPI 1: (Chi,Clo) = bf16-split(acc);
// EPI 2: C = addC + acc / (g_cnt + 1e-6)
// ---------------------------------------------------------------------------
static constexpr int ROWB = 144;
static constexpr int TILEB = 128 * ROWB;          // 18432
static constexpr int BUFB = 2 * TILEB;            // A+B per stage
static constexpr int GSMEM = 2 * BUFB;            // 73728

template <int EPI>
__global__ __launch_bounds__(256) void mma_gemm(
    const __nv_bfloat16* __restrict__ Ah, const __nv_bfloat16* __restrict__ Al,
    const __nv_bfloat16* __restrict__ Bh, const __nv_bfloat16* __restrict__ Bl,
    float* __restrict__ C, __nv_bfloat16* __restrict__ Chi, __nv_bfloat16* __restrict__ Clo,
    const float* __restrict__ addC,
    int K, int ldA, int ldB, int ldC,
    int ksplit, long sA, long sB, long sC, long sAdd, long sSplit, float alpha) {
    extern __shared__ __align__(16) char sm[];
    const uint32_t sbase = smem_u32(sm);
    const int tid = threadIdx.x;
    const int wid = tid >> 5, lane = tid & 31;
    const int warpM = wid & 3, warpN = wid >> 2;

    int bz = blockIdx.z;
    int batch = bz / ksplit;
    int split = bz - batch * ksplit;
    Ah += (long)batch * sA; Al += (long)batch * sA;
    Bh += (long)batch * sB; Bl += (long)batch * sB;
    if (EPI == 1) { Chi += (long)batch * sC; Clo += (long)batch * sC; }
    else C += (long)batch * sC + (long)split * sSplit;
    const int kLen = K / ksplit;
    const long k0 = (long)split * kLen;
    const int rowA = blockIdx.y * 128;
    const int colB = blockIdx.x * 128;

    const int nCk = kLen >> 6;   // K-chunks of 64
    const int nTot = 3 * nCk;

    const int lr = tid >> 3;     // 0..31 (+i*32)
    const int lc = tid & 7;      // 16B chunk within 128B row

    float acc[2][8][4] = {};

    const uint32_t aAddrOff =
        (uint32_t)(warpM * 32 + (lane & 15)) * ROWB + (lane >> 4) * 16;
    const uint32_t bAddrOff =
        (uint32_t)(warpN * 64 + ((lane >> 4) << 3) + (lane & 7)) * ROWB +
        ((lane >> 3) & 1) * 16;

    auto issue_load = [&](int c, int buf) {
        const int pass = c / nCk;
        const int ck = c - pass * nCk;
        const __nv_bfloat16* Ap = (pass == 2) ? Al : Ah;
        const __nv_bfloat16* Bp = (pass == 1) ? Bl : Bh;
        const long kb = k0 + (long)ck * 64;
        uint32_t aT = sbase + buf * BUFB;
        uint32_t bT = aT + TILEB;
#pragma unroll
        for (int i = 0; i < 4; i++) {
            int r = lr + i * 32;
            uint32_t so = (uint32_t)r * ROWB + lc * 16;
            cp16(aT + so, Ap + (long)(rowA + r) * ldA + kb + lc * 8);
            cp16(bT + so, Bp + (long)(colB + r) * ldB + kb + lc * 8);
        }
    };

    issue_load(0, 0);
    cp_commit();

    for (int c = 0; c < nTot; c++) {
        const int buf = c & 1;
        if (c + 1 < nTot) {
            issue_load(c + 1, (c + 1) & 1);
            cp_commit();
            cp_wait1();
        } else {
            cp_wait0();
        }
        __syncthreads();

        uint32_t aT = sbase + buf * BUFB;
        uint32_t bT = aT + TILEB;
#pragma unroll
        for (int ks = 0; ks < 4; ks++) {
            uint32_t af[2][4];
#pragma unroll
            for (int mt = 0; mt < 2; mt++)
                ldsm4(af[mt], aT + aAddrOff + mt * (16 * ROWB) + ks * 32);
            uint32_t bf[8][2];
#pragma unroll
            for (int q = 0; q < 4; q++) {
                uint32_t r4[4];
                ldsm4(r4, bT + bAddrOff + q * (16 * ROWB) + ks * 32);
                bf[2 * q][0] = r4[0]; bf[2 * q][1] = r4[1];
                bf[2 * q + 1][0] = r4[2]; bf[2 * q + 1][1] = r4[3];
            }
#pragma unroll
            for (int mt = 0; mt < 2; mt++)
#pragma unroll
                for (int nt = 0; nt < 8; nt++)
                    mma16816(acc[mt][nt], af[mt], bf[nt]);
        }
        __syncthreads();
    }

    // epilogue
    float scale = (EPI == 2) ? (1.f / (g_cnt + 1e-6f)) : alpha;
    const float* addP = (EPI == 2) ? (addC + (long)batch * sAdd) : nullptr;
#pragma unroll
    for (int mt = 0; mt < 2; mt++) {
        int mrow = rowA + warpM * 32 + mt * 16 + (lane >> 2);
#pragma unroll
        for (int nt = 0; nt < 8; nt++) {
            int ncol = colB + warpN * 64 + nt * 8 + 2 * (lane & 3);
            long i0 = (long)mrow * ldC + ncol;
            long i1 = (long)(mrow + 8) * ldC + ncol;
            float2 v0{acc[mt][nt][0] * scale, acc[mt][nt][1] * scale};
            float2 v1{acc[mt][nt][2] * scale, acc[mt][nt][3] * scale};
            if (EPI == 1) {
                __nv_bfloat16 h0, l0, h1, l1;
                split1(v0.x, h0, l0); split1(v0.y, h1, l1);
                *(__nv_bfloat162*)(Chi + i0) = __nv_bfloat162{h0, h1};
                *(__nv_bfloat162*)(Clo + i0) = __nv_bfloat162{l0, l1};
                split1(v1.x, h0, l0); split1(v1.y, h1, l1);
                *(__nv_bfloat162*)(Chi + i1) = __nv_bfloat162{h0, h1};
                *(__nv_bfloat162*)(Clo + i1) = __nv_bfloat162{l0, l1};
            } else {
                if (EPI == 2) {
                    v0.x += addP[i0]; v0.y += addP[i0 + 1];
                    v1.x += addP[i1]; v1.y += addP[i1 + 1];
                }
                *(float2*)(C + i0) = v0;
                *(float2*)(C + i1) = v1;
            }
        }
    }
}

// ---------------------------------------------------------------------------
extern "C" void kernel_launch(void* const* d_in, const int* in_sizes, int n_in,
                              void* d_out, int out_size) {
    const float* zq = (const float*)d_in[0];
    const float* zs = (const float*)d_in[1];
    const float* zv = (const float*)d_in[2];
    const float* cf = (const float*)d_in[3];
    const float* Wk = (const float*)d_in[4];
    const float* Wv = (const float*)d_in[5];
    const float* Wo = (const float*)d_in[6];
    const float* mem = (const float*)d_in[7];

    float* out = (float*)d_out;
    float* vret = out;
    float* newmem = out + (long)Bn * Dn;

    float *pA2, *pS, *pT;
    cudaGetSymbolAddress((void**)&pA2, g_A2);
    cudaGetSymbolAddress((void**)&pS, g_S);
    cudaGetSymbolAddress((void**)&pT, g_T);

#define SYM(p, s) __nv_bfloat16* p; cudaGetSymbolAddress((void**)&p, s)
    SYM(pWk_h, sWk_h);   SYM(pWk_l, sWk_l);
    SYM(pWkT_h, sWkT_h); SYM(pWkT_l, sWkT_l);
    SYM(pMemT_h, sMemT_h); SYM(pMemT_l, sMemT_l);
    SYM(pWvT_h, sWvT_h); SYM(pWvT_l, sWvT_l);
    SYM(pWoT_h, sWoT_h); SYM(pWoT_l, sWoT_l);
    SYM(pZq_h, sZq_h);   SYM(pZq_l, sZq_l);
    SYM(pZsT_h, sZsT_h); SYM(pZsT_l, sZsT_l);
    SYM(pZvT_h, sZvT_h); SYM(pZvT_l, sZvT_l);
    SYM(pA1_h, sA1_h);   SYM(pA1_l, sA1_l);
    SYM(pA2T_h, sA2T_h); SYM(pA2T_l, sA2T_l);
    SYM(pST_h, sST_h);   SYM(pST_l, sST_l);
    SYM(pT_h, sT_h);     SYM(pT_l, sT_l);
#undef SYM

    cudaFuncSetAttribute(mma_gemm<0>, cudaFuncAttributeMaxDynamicSharedMemorySize, GSMEM);
    cudaFuncSetAttribute(mma_gemm<1>, cudaFuncAttributeMaxDynamicSharedMemorySize, GSMEM);
    cudaFuncSetAttribute(mma_gemm<2>, cudaFuncAttributeMaxDynamicSharedMemorySize, GSMEM);

    dim3 tb(32, 8);

    prep_lam_kernel<<<1, 256>>>(cf);

    // conversions (merged where reads overlap)
    convWk<<<dim3(256, 16), tb>>>(Wk, pWk_h, pWk_l, pWkT_h, pWkT_l);
    splitT<0><<<dim3(16, 256), tb>>>(mem, pMemT_h, pMemT_l, 8192, 512, nullptr);
    splitT<0><<<dim3(256, 16), tb>>>(Wv, pWvT_h, pWvT_l, 512, 8192, nullptr);
    splitT<0><<<dim3(16, 16), tb>>>(Wo, pWoT_h, pWoT_l, 512, 512, nullptr);
    convZ<<<dim3(16, 128), tb>>>(zq, zs, zv, pZq_h, pZq_l, pZsT_h, pZsT_l, pZvT_h, pZvT_l);

    // 1) A1 = Wk @ mem_flat   (K=8192, 8-way K-split -> 128 CTAs, 1 wave)
    mma_gemm<0><<<dim3(4, 4, 8), 256, GSMEM>>>(pWk_h, pWk_l, pMemT_h, pMemT_l,
        pT, nullptr, nullptr, nullptr, 8192, 8192, 8192, 512, 8, 0, 0, 0, 0, DD, 1.f);
    reduce_split<<<(Dn * Dn + 255) / 256, 256>>>(pT, pA1_h, pA1_l, Dn * Dn, 8);

    // 2) A2 = (A1 @ Wo) / H   (4-way K-split)
    mma_gemm<0><<<dim3(4, 4, 4), 256, GSMEM>>>(pA1_h, pA1_l, pWoT_h, pWoT_l,
        pT, nullptr, nullptr, nullptr, 512, 512, 512, 512, 4, 0, 0, 0, 0, DD, 1.f / Hn);
    reduce_partials<<<(Dn * Dn + 255) / 256, 256>>>(pT, pA2, Dn * Dn, 4);
    splitT<0><<<dim3(16, 16), tb>>>(pA2, pA2T_h, pA2T_l, 512, 512, nullptr);

    // 3) v_ret = zq @ A2   (128 CTAs, 1 wave)
    mma_gemm<0><<<dim3(4, 32, 1), 256, GSMEM>>>(pZq_h, pZq_l, pA2T_h, pA2T_l,
        vret, nullptr, nullptr, nullptr, 512, 512, 512, 512, 1, 0, 0, 0, 0, 0, 1.f);

    // 4) S = zs^T diag(lam) zv   (K=4096, 8-way K-split -> 128 CTAs)
    mma_gemm<0><<<dim3(4, 4, 8), 256, GSMEM>>>(pZsT_h, pZsT_l, pZvT_h, pZvT_l,
        pT, nullptr, nullptr, nullptr, 4096, 4096, 4096, 512, 8, 0, 0, 0, 0, DD, 1.f);
    reduce_partials<<<(Dn * Dn + 255) / 256, 256>>>(pT, pS, Dn * Dn, 8);
    splitT<0><<<dim3(16, 16), tb>>>(pS, pST_h, pST_l, 512, 512, nullptr);

    // 5) T_h = Wk_h^T @ S   (batched over heads; bf16 hi/lo epilogue)
    mma_gemm<1><<<dim3(4, 4, 16), 256, GSMEM>>>(pWkT_h, pWkT_l, pST_h, pST_l,
        nullptr, pT_h, pT_l, nullptr, 512, 512, 512, 512, 1, DD, 0, DD, 0, 0, 1.f);

    // 6) new_mem_h = mem_h + (T_h @ Wv_h) / (cnt + 1e-6)
    mma_gemm<2><<<dim3(4, 4, 16), 256, GSMEM>>>(pT_h, pT_l, pWvT_h, pWvT_l,
        newmem, nullptr, nullptr, mem, 512, 512, 512, 512, 1, DD, DD, DD, DD, 0, 1.f);
}

// round 7
// speedup vs baseline: 2.2798x; 1.1350x over previous
#include <cuda_runtime.h>
#include <cuda_bf16.h>
#include <cstdint>

static constexpr int Bn = 4096;
static constexpr int Dn = 512;
static constexpr int Hn = 16;
static constexpr long DD = (long)Dn * Dn;

// ---------------------------------------------------------------------------
// Device scratch
// ---------------------------------------------------------------------------
__device__ float g_T[Hn * Dn * Dn];     // fp32 K-split partials
__device__ float g_lam[Bn];
__device__ float g_cnt;

#define BF16_SCRATCH(name, n) __device__ __align__(16) __nv_bfloat16 name[n]
BF16_SCRATCH(sWk_h, 512 * 8192);  BF16_SCRATCH(sWk_l, 512 * 8192);
BF16_SCRATCH(sWkT_h, 8192 * 512); BF16_SCRATCH(sWkT_l, 8192 * 512);
BF16_SCRATCH(sMemT_h, 512 * 8192);BF16_SCRATCH(sMemT_l, 512 * 8192);
BF16_SCRATCH(sWvT_h, 8192 * 512); BF16_SCRATCH(sWvT_l, 8192 * 512);
BF16_SCRATCH(sWoT_h, 512 * 512);  BF16_SCRATCH(sWoT_l, 512 * 512);
BF16_SCRATCH(sZq_h, 4096 * 512);  BF16_SCRATCH(sZq_l, 4096 * 512);
BF16_SCRATCH(sZsT_h, 512 * 4096); BF16_SCRATCH(sZsT_l, 512 * 4096);
BF16_SCRATCH(sZvT_h, 512 * 4096); BF16_SCRATCH(sZvT_l, 512 * 4096);
BF16_SCRATCH(sA1_h, 512 * 512);   BF16_SCRATCH(sA1_l, 512 * 512);
BF16_SCRATCH(sA2T_h, 512 * 512);  BF16_SCRATCH(sA2T_l, 512 * 512);
BF16_SCRATCH(sST_h, 512 * 512);   BF16_SCRATCH(sST_l, 512 * 512);
BF16_SCRATCH(sT_h, 16 * 512 * 512); BF16_SCRATCH(sT_l, 16 * 512 * 512);

// ---------------------------------------------------------------------------
// helpers
// ---------------------------------------------------------------------------
__device__ __forceinline__ uint32_t smem_u32(const void* p) {
    uint32_t a;
    asm("{ .reg .u64 t; cvta.to.shared.u64 t, %1; cvt.u32.u64 %0, t; }"
        : "=r"(a) : "l"(p));
    return a;
}
__device__ __forceinline__ void ldsm4(uint32_t* r, uint32_t addr) {
    asm volatile("ldmatrix.sync.aligned.m8n8.x4.shared.b16 {%0,%1,%2,%3}, [%4];"
                 : "=r"(r[0]), "=r"(r[1]), "=r"(r[2]), "=r"(r[3]) : "r"(addr));
}
__device__ __forceinline__ void mma16816(float* c, const uint32_t* a, const uint32_t* b) {
    asm volatile(
        "mma.sync.aligned.m16n8k16.row.col.f32.bf16.bf16.f32 "
        "{%0,%1,%2,%3}, {%4,%5,%6,%7}, {%8,%9}, {%0,%1,%2,%3};"
        : "+f"(c[0]), "+f"(c[1]), "+f"(c[2]), "+f"(c[3])
        : "r"(a[0]), "r"(a[1]), "r"(a[2]), "r"(a[3]), "r"(b[0]), "r"(b[1]));
}
__device__ __forceinline__ void cp16(uint32_t dst, const void* src) {
    asm volatile("cp.async.cg.shared.global [%0], [%1], 16;" :: "r"(dst), "l"(src));
}
__device__ __forceinline__ void cp_commit() { asm volatile("cp.async.commit_group;"); }
__device__ __forceinline__ void cp_wait1() { asm volatile("cp.async.wait_group 1;"); }
__device__ __forceinline__ void cp_wait0() { asm volatile("cp.async.wait_group 0;"); }

__device__ __forceinline__ void split1(float v, __nv_bfloat16& h, __nv_bfloat16& l) {
    h = __float2bfloat16(v);
    l = __float2bfloat16(v - __bfloat162float(h));
}

// ---------------------------------------------------------------------------
// lam prep
// ---------------------------------------------------------------------------
__global__ void prep_lam_kernel(const float* __restrict__ conf) {
    int t = threadIdx.x;
    float local = 0.f;
    for (int i = t; i < Bn; i += 256) {
        float lam = fminf(fmaxf(1.0f - conf[i], 0.f), 1.f);
        float m = (lam > 0.3f) ? 1.f : 0.f;
        g_lam[i] = lam * m;
        local += m;
    }
#pragma unroll
    for (int o = 16; o > 0; o >>= 1) local += __shfl_down_sync(0xffffffffu, local, o);
    __shared__ float ws[8];
    if ((t & 31) == 0) ws[t >> 5] = local;
    __syncthreads();
    if (t == 0) {
        float s = 0.f;
#pragma unroll
        for (int w = 0; w < 8; w++) s += ws[w];
        g_cnt = s;
    }
}

// sum K-split partials -> bf16 hi/lo (direct layout)
__global__ void reduce_split(const float* __restrict__ part, __nv_bfloat16* __restrict__ hi,
                             __nv_bfloat16* __restrict__ lo, int nElem, int nPart) {
    int i = blockIdx.x * blockDim.x + threadIdx.x;
    if (i < nElem) {
        float s = 0.f;
        for (int p = 0; p < nPart; p++) s += part[(long)p * nElem + i];
        __nv_bfloat16 h, l;
        split1(s, h, l);
        hi[i] = h; lo[i] = l;
    }
}

// sum K-split partials (512x512) -> TRANSPOSED bf16 hi/lo
__global__ void reduce_splitT(const float* __restrict__ part, __nv_bfloat16* __restrict__ hi,
                              __nv_bfloat16* __restrict__ lo, int nPart) {
    __shared__ float t[32][33];
    int c0 = blockIdx.x * 32, r0 = blockIdx.y * 32;
    int tx = threadIdx.x, ty = threadIdx.y;  // 32x8
#pragma unroll
    for (int i = 0; i < 32; i += 8) {
        long o = (long)(r0 + ty + i) * 512 + c0 + tx;
        float s = 0.f;
        for (int p = 0; p < nPart; p++) s += part[(long)p * DD + o];
        t[ty + i][tx] = s;
    }
    __syncthreads();
#pragma unroll
    for (int i = 0; i < 32; i += 8) {
        float v = t[tx][ty + i];
        long o = (long)(c0 + ty + i) * 512 + r0 + tx;
        __nv_bfloat16 h, l;
        split1(v, h, l);
        hi[o] = h; lo[o] = l;
    }
}

// fp32 [R,C] -> transposed bf16 hi/lo [C,R].  64x64 tiles, bf16x2 writes.
__global__ void splitT64(const float* __restrict__ src, __nv_bfloat16* __restrict__ hi,
                         __nv_bfloat16* __restrict__ lo, int R, int C) {
    __shared__ float t[64][65];
    int c0 = blockIdx.x * 64, r0 = blockIdx.y * 64;
    int tx = threadIdx.x, ty = threadIdx.y;  // 32x8
#pragma unroll
    for (int j = 0; j < 8; j++) {
        int row = ty + j * 8;
        float2 v = *(const float2*)(src + (long)(r0 + row) * C + c0 + 2 * tx);
        t[row][2 * tx] = v.x; t[row][2 * tx + 1] = v.y;
    }
    __syncthreads();
#pragma unroll
    for (int j = 0; j < 8; j++) {
        int c = ty + j * 8;
        float v0 = t[2 * tx][c], v1 = t[2 * tx + 1][c];
        long o = (long)(c0 + c) * R + r0 + 2 * tx;
        __nv_bfloat16 h0, l0, h1, l1;
        split1(v0, h0, l0); split1(v1, h1, l1);
        *(__nv_bfloat162*)(hi + o) = __nv_bfloat162{h0, h1};
        *(__nv_bfloat162*)(lo + o) = __nv_bfloat162{l0, l1};
    }
}

// Wk (512x8192): one read -> direct split + transposed split (vectorized)
__global__ void convWk(const float* __restrict__ src,
                       __nv_bfloat16* __restrict__ dh, __nv_bfloat16* __restrict__ dl,
                       __nv_bfloat16* __restrict__ th, __nv_bfloat16* __restrict__ tl) {
    __shared__ float t[64][65];
    const int R = 512, C = 8192;
    int c0 = blockIdx.x * 64, r0 = blockIdx.y * 64;
    int tx = threadIdx.x, ty = threadIdx.y;
#pragma unroll
    for (int j = 0; j < 8; j++) {
        int row = ty + j * 8;
        long o = (long)(r0 + row) * C + c0 + 2 * tx;
        float2 v = *(const float2*)(src + o);
        t[row][2 * tx] = v.x; t[row][2 * tx + 1] = v.y;
        __nv_bfloat16 h0, l0, h1, l1;
        split1(v.x, h0, l0); split1(v.y, h1, l1);
        *(__nv_bfloat162*)(dh + o) = __nv_bfloat162{h0, h1};
        *(__nv_bfloat162*)(dl + o) = __nv_bfloat162{l0, l1};
    }
    __syncthreads();
#pragma unroll
    for (int j = 0; j < 8; j++) {
        int c = ty + j * 8;
        float v0 = t[2 * tx][c], v1 = t[2 * tx + 1][c];
        long o = (long)(c0 + c) * R + r0 + 2 * tx;
        __nv_bfloat16 h0, l0, h1, l1;
        split1(v0, h0, l0); split1(v1, h1, l1);
        *(__nv_bfloat162*)(th + o) = __nv_bfloat162{h0, h1};
        *(__nv_bfloat162*)(tl + o) = __nv_bfloat162{l0, l1};
    }
}

// zq direct + zs (lam-scaled, transposed) + zv (transposed). 4096x512.
__global__ void convZ(const float* __restrict__ zq, const float* __restrict__ zs,
                      const float* __restrict__ zv,
                      __nv_bfloat16* __restrict__ qh, __nv_bfloat16* __restrict__ ql,
                      __nv_bfloat16* __restrict__ sh, __nv_bfloat16* __restrict__ sl,
                      __nv_bfloat16* __restrict__ vh, __nv_bfloat16* __restrict__ vl) {
    __shared__ float ts[64][65], tv[64][65];
    const int R = 4096, C = 512;
    int c0 = blockIdx.x * 64, r0 = blockIdx.y * 64;
    int tx = threadIdx.x, ty = threadIdx.y;
#pragma unroll
    for (int j = 0; j < 8; j++) {
        int row = ty + j * 8;
        int r = r0 + row;
        long o = (long)r * C + c0 + 2 * tx;
        float lam = g_lam[r];
        float2 q = *(const float2*)(zq + o);
        __nv_bfloat16 h0, l0, h1, l1;
        split1(q.x, h0, l0); split1(q.y, h1, l1);
        *(__nv_bfloat162*)(qh + o) = __nv_bfloat162{h0, h1};
        *(__nv_bfloat162*)(ql + o) = __nv_bfloat162{l0, l1};
        float2 s = *(const float2*)(zs + o);
        ts[row][2 * tx] = s.x * lam; ts[row][2 * tx + 1] = s.y * lam;
        float2 v = *(const float2*)(zv + o);
        tv[row][2 * tx] = v.x; tv[row][2 * tx + 1] = v.y;
    }
    __syncthreads();
#pragma unroll
    for (int j = 0; j < 8; j++) {
        int c = ty + j * 8;
        long o = (long)(c0 + c) * R + r0 + 2 * tx;
        __nv_bfloat16 h0, l0, h1, l1;
        split1(ts[2 * tx][c], h0, l0); split1(ts[2 * tx + 1][c], h1, l1);
        *(__nv_bfloat162*)(sh + o) = __nv_bfloat162{h0, h1};
        *(__nv_bfloat162*)(sl + o) = __nv_bfloat162{l0, l1};
        split1(tv[2 * tx][c], h0, l0); split1(tv[2 * tx + 1][c], h1, l1);
        *(__nv_bfloat162*)(vh + o) = __nv_bfloat162{h0, h1};
        *(__nv_bfloat162*)(vl + o) = __nv_bfloat162{l0, l1};
    }
}

// ---------------------------------------------------------------------------
// HMMA bf16-split GEMM, fused 3-pass mainloop: per 64-K-chunk, load
// Ah/Al/Bh/Bl tiles once and issue hh+hl+lh MMA combos.
// 128x128 tile, 8 warps (4x2), warp tile 32x64, 2-stage cp.async pipeline.
// EPI 0: C (fp32) = alpha*acc;  EPI 1: (Chi,Clo) = bf16-split(acc);
// EPI 2: C = addC + acc / (g_cnt + 1e-6)
// ---------------------------------------------------------------------------
static constexpr int ROWB = 144;
static constexpr int TILEB = 128 * ROWB;          // 18432
static constexpr int BUFB = 4 * TILEB;            // Ah+Al+Bh+Bl per stage
static constexpr int GSMEM = 2 * BUFB;            // 147456

template <int EPI>
__global__ __launch_bounds__(256) void mma_gemm(
    const __nv_bfloat16* __restrict__ Ah, const __nv_bfloat16* __restrict__ Al,
    const __nv_bfloat16* __restrict__ Bh, const __nv_bfloat16* __restrict__ Bl,
    float* __restrict__ C, __nv_bfloat16* __restrict__ Chi, __nv_bfloat16* __restrict__ Clo,
    const float* __restrict__ addC,
    int K, int ldA, int ldB, int ldC,
    int ksplit, long sA, long sB, long sC, long sAdd, long sSplit, float alpha) {
    extern __shared__ __align__(16) char sm[];
    const uint32_t sbase = smem_u32(sm);
    const int tid = threadIdx.x;
    const int wid = tid >> 5, lane = tid & 31;
    const int warpM = wid & 3, warpN = wid >> 2;

    int bz = blockIdx.z;
    int batch = bz / ksplit;
    int split = bz - batch * ksplit;
    Ah += (long)batch * sA; Al += (long)batch * sA;
    Bh += (long)batch * sB; Bl += (long)batch * sB;
    if (EPI == 1) { Chi += (long)batch * sC; Clo += (long)batch * sC; }
    else C += (long)batch * sC + (long)split * sSplit;
    const int kLen = K / ksplit;
    const long k0 = (long)split * kLen;
    const int rowA = blockIdx.y * 128;
    const int colB = blockIdx.x * 128;

    const int nCk = kLen >> 6;   // 64-wide K chunks

    const int lr = tid >> 3;     // 0..31 (+i*32)
    const int lc = tid & 7;      // 16B chunk within 128B row

    float acc[2][8][4] = {};

    const uint32_t aAddrOff =
        (uint32_t)(warpM * 32 + (lane & 15)) * ROWB + (lane >> 4) * 16;
    const uint32_t bAddrOff =
        (uint32_t)(warpN * 64 + ((lane >> 4) << 3) + (lane & 7)) * ROWB +
        ((lane >> 3) & 1) * 16;

    auto issue_load = [&](int ck, int buf) {
        const long kb = k0 + (long)ck * 64;
        uint32_t base = sbase + buf * BUFB;
#pragma unroll
        for (int i = 0; i < 4; i++) {
            int r = lr + i * 32;
            uint32_t so = (uint32_t)r * ROWB + lc * 16;
            long ao = (long)(rowA + r) * ldA + kb + lc * 8;
            long bo = (long)(colB + r) * ldB + kb + lc * 8;
            cp16(base + so, Ah + ao);
            cp16(base + TILEB + so, Al + ao);
            cp16(base + 2 * TILEB + so, Bh + bo);
            cp16(base + 3 * TILEB + so, Bl + bo);
        }
    };

    issue_load(0, 0);
    cp_commit();

    for (int c = 0; c < nCk; c++) {
        const int buf = c & 1;
        if (c + 1 < nCk) {
            issue_load(c + 1, (c + 1) & 1);
            cp_commit();
            cp_wait1();
        } else {
            cp_wait0();
        }
        __syncthreads();

        uint32_t aH = sbase + buf * BUFB;
        uint32_t aL = aH + TILEB;
        uint32_t bH = aL + TILEB;
        uint32_t bL = bH + TILEB;
#pragma unroll
        for (int ks = 0; ks < 4; ks++) {
            uint32_t afh[2][4], afl[2][4];
#pragma unroll
            for (int mt = 0; mt < 2; mt++) {
                ldsm4(afh[mt], aH + aAddrOff + mt * (16 * ROWB) + ks * 32);
                ldsm4(afl[mt], aL + aAddrOff + mt * (16 * ROWB) + ks * 32);
            }
            uint32_t bfh[8][2], bfl[8][2];
#pragma unroll
            for (int q = 0; q < 4; q++) {
                uint32_t r4[4];
                ldsm4(r4, bH + bAddrOff + q * (16 * ROWB) + ks * 32);
                bfh[2 * q][0] = r4[0]; bfh[2 * q][1] = r4[1];
                bfh[2 * q + 1][0] = r4[2]; bfh[2 * q + 1][1] = r4[3];
                ldsm4(r4, bL + bAddrOff + q * (16 * ROWB) + ks * 32);
                bfl[2 * q][0] = r4[0]; bfl[2 * q][1] = r4[1];
                bfl[2 * q + 1][0] = r4[2]; bfl[2 * q + 1][1] = r4[3];
            }
#pragma unroll
            for (int mt = 0; mt < 2; mt++)
#pragma unroll
                for (int nt = 0; nt < 8; nt++) {
                    mma16816(acc[mt][nt], afh[mt], bfh[nt]);
                    mma16816(acc[mt][nt], afh[mt], bfl[nt]);
                    mma16816(acc[mt][nt], afl[mt], bfh[nt]);
                }
        }
        __syncthreads();
    }

    // epilogue
    float scale = (EPI == 2) ? (1.f / (g_cnt + 1e-6f)) : alpha;
    const float* addP = (EPI == 2) ? (addC + (long)batch * sAdd) : nullptr;
#pragma unroll
    for (int mt = 0; mt < 2; mt++) {
        int mrow = rowA + warpM * 32 + mt * 16 + (lane >> 2);
#pragma unroll
        for (int nt = 0; nt < 8; nt++) {
            int ncol = colB + warpN * 64 + nt * 8 + 2 * (lane & 3);
            long i0 = (long)mrow * ldC + ncol;
            long i1 = (long)(mrow + 8) * ldC + ncol;
            float2 v0{acc[mt][nt][0] * scale, acc[mt][nt][1] * scale};
            float2 v1{acc[mt][nt][2] * scale, acc[mt][nt][3] * scale};
            if (EPI == 1) {
                __nv_bfloat16 h0, l0, h1, l1;
                split1(v0.x, h0, l0); split1(v0.y, h1, l1);
                *(__nv_bfloat162*)(Chi + i0) = __nv_bfloat162{h0, h1};
                *(__nv_bfloat162*)(Clo + i0) = __nv_bfloat162{l0, l1};
                split1(v1.x, h0, l0); split1(v1.y, h1, l1);
                *(__nv_bfloat162*)(Chi + i1) = __nv_bfloat162{h0, h1};
                *(__nv_bfloat162*)(Clo + i1) = __nv_bfloat162{l0, l1};
            } else {
                if (EPI == 2) {
                    v0.x += addP[i0]; v0.y += addP[i0 + 1];
                    v1.x += addP[i1]; v1.y += addP[i1 + 1];
                }
                *(float2*)(C + i0) = v0;
                *(float2*)(C + i1) = v1;
            }
        }
    }
}

// ---------------------------------------------------------------------------
extern "C" void kernel_launch(void* const* d_in, const int* in_sizes, int n_in,
                              void* d_out, int out_size) {
    const float* zq = (const float*)d_in[0];
    const float* zs = (const float*)d_in[1];
    const float* zv = (const float*)d_in[2];
    const float* cf = (const float*)d_in[3];
    const float* Wk = (const float*)d_in[4];
    const float* Wv = (const float*)d_in[5];
    const float* Wo = (const float*)d_in[6];
    const float* mem = (const float*)d_in[7];

    float* out = (float*)d_out;
    float* vret = out;
    float* newmem = out + (long)Bn * Dn;

    float* pT;
    cudaGetSymbolAddress((void**)&pT, g_T);

#define SYM(p, s) __nv_bfloat16* p; cudaGetSymbolAddress((void**)&p, s)
    SYM(pWk_h, sWk_h);   SYM(pWk_l, sWk_l);
    SYM(pWkT_h, sWkT_h); SYM(pWkT_l, sWkT_l);
    SYM(pMemT_h, sMemT_h); SYM(pMemT_l, sMemT_l);
    SYM(pWvT_h, sWvT_h); SYM(pWvT_l, sWvT_l);
    SYM(pWoT_h, sWoT_h); SYM(pWoT_l, sWoT_l);
    SYM(pZq_h, sZq_h);   SYM(pZq_l, sZq_l);
    SYM(pZsT_h, sZsT_h); SYM(pZsT_l, sZsT_l);
    SYM(pZvT_h, sZvT_h); SYM(pZvT_l, sZvT_l);
    SYM(pA1_h, sA1_h);   SYM(pA1_l, sA1_l);
    SYM(pA2T_h, sA2T_h); SYM(pA2T_l, sA2T_l);
    SYM(pST_h, sST_h);   SYM(pST_l, sST_l);
    SYM(pT_h, sT_h);     SYM(pT_l, sT_l);
#undef SYM

    cudaFuncSetAttribute(mma_gemm<0>, cudaFuncAttributeMaxDynamicSharedMemorySize, GSMEM);
    cudaFuncSetAttribute(mma_gemm<1>, cudaFuncAttributeMaxDynamicSharedMemorySize, GSMEM);
    cudaFuncSetAttribute(mma_gemm<2>, cudaFuncAttributeMaxDynamicSharedMemorySize, GSMEM);

    dim3 tb(32, 8);

    prep_lam_kernel<<<1, 256>>>(cf);

    // conversions (vectorized 64x64 tiles)
    convWk<<<dim3(128, 8), tb>>>(Wk, pWk_h, pWk_l, pWkT_h, pWkT_l);
    splitT64<<<dim3(8, 128), tb>>>(mem, pMemT_h, pMemT_l, 8192, 512);
    splitT64<<<dim3(128, 8), tb>>>(Wv, pWvT_h, pWvT_l, 512, 8192);
    splitT64<<<dim3(8, 8), tb>>>(Wo, pWoT_h, pWoT_l, 512, 512);
    convZ<<<dim3(8, 64), tb>>>(zq, zs, zv, pZq_h, pZq_l, pZsT_h, pZsT_l, pZvT_h, pZvT_l);

    // 1) A1 = Wk @ mem_flat   (K=8192, 8-way K-split -> 128 CTAs, 1 wave)
    mma_gemm<0><<<dim3(4, 4, 8), 256, GSMEM>>>(pWk_h, pWk_l, pMemT_h, pMemT_l,
        pT, nullptr, nullptr, nullptr, 8192, 8192, 8192, 512, 8, 0, 0, 0, 0, DD, 1.f);
    reduce_split<<<(Dn * Dn + 255) / 256, 256>>>(pT, pA1_h, pA1_l, Dn * Dn, 8);

    // 2) A2 = (A1 @ Wo) / H   (4-way K-split; fused reduce+transpose+split)
    mma_gemm<0><<<dim3(4, 4, 4), 256, GSMEM>>>(pA1_h, pA1_l, pWoT_h, pWoT_l,
        pT, nullptr, nullptr, nullptr, 512, 512, 512, 512, 4, 0, 0, 0, 0, DD, 1.f / Hn);
    reduce_splitT<<<dim3(16, 16), tb>>>(pT, pA2T_h, pA2T_l, 4);

    // 3) v_ret = zq @ A2   (128 CTAs, 1 wave)
    mma_gemm<0><<<dim3(4, 32, 1), 256, GSMEM>>>(pZq_h, pZq_l, pA2T_h, pA2T_l,
        vret, nullptr, nullptr, nullptr, 512, 512, 512, 512, 1, 0, 0, 0, 0, 0, 1.f);

    // 4) S = zs^T diag(lam) zv   (K=4096, 8-way K-split; fused reduce+T+split)
    mma_gemm<0><<<dim3(4, 4, 8), 256, GSMEM>>>(pZsT_h, pZsT_l, pZvT_h, pZvT_l,
        pT, nullptr, nullptr, nullptr, 4096, 4096, 4096, 512, 8, 0, 0, 0, 0, DD, 1.f);
    reduce_splitT<<<dim3(16, 16), tb>>>(pT, pST_h, pST_l, 8);

    // 5) T_h = Wk_h^T @ S   (batched over heads; bf16 hi/lo epilogue)
    mma_gemm<1><<<dim3(4, 4, 16), 256, GSMEM>>>(pWkT_h, pWkT_l, pST_h, pST_l,
        nullptr, pT_h, pT_l, nullptr, 512, 512, 512, 512, 1, DD, 0, DD, 0, 0, 1.f);

    // 6) new_mem_h = mem_h + (T_h @ Wv_h) / (cnt + 1e-6)
    mma_gemm<2><<<dim3(4, 4, 16), 256, GSMEM>>>(pT_h, pT_l, pWvT_h, pWvT_l,
        newmem, nullptr, nullptr, mem, 512, 512, 512, 512, 1, DD, DD, DD, DD, 0, 1.f);
}

// round 10
// speedup vs baseline: 2.3505x; 1.0310x over previous
#include <cuda_runtime.h>
#include <cuda_bf16.h>
#include <cstdint>

static constexpr int Bn = 4096;
static constexpr int Dn = 512;
static constexpr int Hn = 16;
static constexpr long DD = (long)Dn * Dn;

// ---------------------------------------------------------------------------
// Device scratch
// ---------------------------------------------------------------------------
__device__ float g_T[2 * 8 * Dn * Dn];  // fp32 K-split partials (two banks of 8)
__device__ float g_lam[Bn];
__device__ float g_cnt;

#define BF16_SCRATCH(name, n) __device__ __align__(16) __nv_bfloat16 name[n]
BF16_SCRATCH(sWk_h, 512 * 8192);  BF16_SCRATCH(sWk_l, 512 * 8192);
BF16_SCRATCH(sWkT_h, 8192 * 512); BF16_SCRATCH(sWkT_l, 8192 * 512);
BF16_SCRATCH(sMemT_h, 512 * 8192);BF16_SCRATCH(sMemT_l, 512 * 8192);
BF16_SCRATCH(sWvT_h, 8192 * 512); BF16_SCRATCH(sWvT_l, 8192 * 512);
BF16_SCRATCH(sWoT_h, 512 * 512);  BF16_SCRATCH(sWoT_l, 512 * 512);
BF16_SCRATCH(sZq_h, 4096 * 512);  BF16_SCRATCH(sZq_l, 4096 * 512);
BF16_SCRATCH(sZsT_h, 512 * 4096); BF16_SCRATCH(sZsT_l, 512 * 4096);
BF16_SCRATCH(sZvT_h, 512 * 4096); BF16_SCRATCH(sZvT_l, 512 * 4096);
BF16_SCRATCH(sA1_h, 512 * 512);   BF16_SCRATCH(sA1_l, 512 * 512);
BF16_SCRATCH(sA2T_h, 512 * 512);  BF16_SCRATCH(sA2T_l, 512 * 512);
BF16_SCRATCH(sST_h, 512 * 512);   BF16_SCRATCH(sST_l, 512 * 512);
BF16_SCRATCH(sT_h, 16 * 512 * 512); BF16_SCRATCH(sT_l, 16 * 512 * 512);

// ---------------------------------------------------------------------------
// helpers
// ---------------------------------------------------------------------------
__device__ __forceinline__ uint32_t smem_u32(const void* p) {
    uint32_t a;
    asm("{ .reg .u64 t; cvta.to.shared.u64 t, %1; cvt.u32.u64 %0, t; }"
        : "=r"(a) : "l"(p));
    return a;
}
__device__ __forceinline__ void ldsm4(uint32_t* r, uint32_t addr) {
    asm volatile("ldmatrix.sync.aligned.m8n8.x4.shared.b16 {%0,%1,%2,%3}, [%4];"
                 : "=r"(r[0]), "=r"(r[1]), "=r"(r[2]), "=r"(r[3]) : "r"(addr));
}
__device__ __forceinline__ void mma16816(float* c, const uint32_t* a, const uint32_t* b) {
    asm volatile(
        "mma.sync.aligned.m16n8k16.row.col.f32.bf16.bf16.f32 "
        "{%0,%1,%2,%3}, {%4,%5,%6,%7}, {%8,%9}, {%0,%1,%2,%3};"
        : "+f"(c[0]), "+f"(c[1]), "+f"(c[2]), "+f"(c[3])
        : "r"(a[0]), "r"(a[1]), "r"(a[2]), "r"(a[3]), "r"(b[0]), "r"(b[1]));
}
__device__ __forceinline__ void cp16(uint32_t dst, const void* src) {
    asm volatile("cp.async.cg.shared.global [%0], [%1], 16;" :: "r"(dst), "l"(src));
}
__device__ __forceinline__ void cp_commit() { asm volatile("cp.async.commit_group;"); }
__device__ __forceinline__ void cp_wait1() { asm volatile("cp.async.wait_group 1;"); }
__device__ __forceinline__ void cp_wait0() { asm volatile("cp.async.wait_group 0;"); }

__device__ __forceinline__ void split1(float v, __nv_bfloat16& h, __nv_bfloat16& l) {
    h = __float2bfloat16(v);
    l = __float2bfloat16(v - __bfloat162float(h));
}
__device__ __forceinline__ uint32_t pack2(float a, float b, float& ra, float& rb) {
    __nv_bfloat162 p{__float2bfloat16(a), __float2bfloat16(b)};
    ra = a - __bfloat162float(p.x);
    rb = b - __bfloat162float(p.y);
    return *(uint32_t*)&p;
}
__device__ __forceinline__ uint32_t pack2lo(float a, float b) {
    __nv_bfloat162 p{__float2bfloat16(a), __float2bfloat16(b)};
    return *(uint32_t*)&p;
}

// ---------------------------------------------------------------------------
// lam prep
// ---------------------------------------------------------------------------
__global__ void prep_lam_kernel(const float* __restrict__ conf) {
    int t = threadIdx.x;
    float local = 0.f;
    for (int i = t; i < Bn; i += 256) {
        float lam = fminf(fmaxf(1.0f - conf[i], 0.f), 1.f);
        float m = (lam > 0.3f) ? 1.f : 0.f;
        g_lam[i] = lam * m;
        local += m;
    }
#pragma unroll
    for (int o = 16; o > 0; o >>= 1) local += __shfl_down_sync(0xffffffffu, local, o);
    __shared__ float ws[8];
    if ((t & 31) == 0) ws[t >> 5] = local;
    __syncthreads();
    if (t == 0) {
        float s = 0.f;
#pragma unroll
        for (int w = 0; w < 8; w++) s += ws[w];
        g_cnt = s;
    }
}

// sum K-split partials -> bf16 hi/lo (direct layout)
__global__ void reduce_split(const float* __restrict__ part, __nv_bfloat16* __restrict__ hi,
                             __nv_bfloat16* __restrict__ lo, int nElem, int nPart) {
    int i = blockIdx.x * blockDim.x + threadIdx.x;
    if (i < nElem) {
        float s = 0.f;
        for (int p = 0; p < nPart; p++) s += part[(long)p * nElem + i];
        __nv_bfloat16 h, l;
        split1(s, h, l);
        hi[i] = h; lo[i] = l;
    }
}

// sum K-split partials (512x512) -> TRANSPOSED bf16 hi/lo
__global__ void reduce_splitT(const float* __restrict__ part, __nv_bfloat16* __restrict__ hi,
                              __nv_bfloat16* __restrict__ lo, int nPart) {
    __shared__ float t[32][33];
    int c0 = blockIdx.x * 32, r0 = blockIdx.y * 32;
    int tx = threadIdx.x, ty = threadIdx.y;  // 32x8
#pragma unroll
    for (int i = 0; i < 32; i += 8) {
        long o = (long)(r0 + ty + i) * 512 + c0 + tx;
        float s = 0.f;
        for (int p = 0; p < nPart; p++) s += part[(long)p * DD + o];
        t[ty + i][tx] = s;
    }
    __syncthreads();
#pragma unroll
    for (int i = 0; i < 32; i += 8) {
        float v = t[tx][ty + i];
        long o = (long)(c0 + ty + i) * 512 + r0 + tx;
        __nv_bfloat16 h, l;
        split1(v, h, l);
        hi[o] = h; lo[o] = l;
    }
}

// ---------------------------------------------------------------------------
// Vectorized conversions: 64x64 tiles, float4 loads, uint2 (4 x bf16) stores.
// ---------------------------------------------------------------------------
__global__ void transSplit4(const float* __restrict__ src, __nv_bfloat16* __restrict__ hi,
                            __nv_bfloat16* __restrict__ lo, int R, int C) {
    __shared__ float t[64][65];
    int c0 = blockIdx.x * 64, r0 = blockIdx.y * 64;
    int tid = threadIdx.x;
    int f4 = tid & 15, row4 = tid >> 4;
#pragma unroll
    for (int j = 0; j < 4; j++) {
        int row = row4 + 16 * j;
        float4 v = *(const float4*)(src + (long)(r0 + row) * C + c0 + f4 * 4);
        t[row][f4 * 4] = v.x; t[row][f4 * 4 + 1] = v.y;
        t[row][f4 * 4 + 2] = v.z; t[row][f4 * 4 + 3] = v.w;
    }
    __syncthreads();
    int rg = tid & 15, cl = tid >> 4;
#pragma unroll
    for (int p = 0; p < 4; p++) {
        int c = cl + 16 * p;
        float v0 = t[4 * rg][c], v1 = t[4 * rg + 1][c];
        float v2 = t[4 * rg + 2][c], v3 = t[4 * rg + 3][c];
        float l0, l1, l2, l3;
        uint2 uh{pack2(v0, v1, l0, l1), pack2(v2, v3, l2, l3)};
        uint2 ul{pack2lo(l0, l1), pack2lo(l2, l3)};
        long o = (long)(c0 + c) * R + r0 + 4 * rg;
        *(uint2*)(hi + o) = uh;
        *(uint2*)(lo + o) = ul;
    }
}

// Wk (512x8192): one read -> direct split + transposed split
__global__ void convWk4(const float* __restrict__ src,
                        __nv_bfloat16* __restrict__ dh, __nv_bfloat16* __restrict__ dl,
                        __nv_bfloat16* __restrict__ th, __nv_bfloat16* __restrict__ tl) {
    __shared__ float t[64][65];
    const int R = 512, C = 8192;
    int c0 = blockIdx.x * 64, r0 = blockIdx.y * 64;
    int tid = threadIdx.x;
    int f4 = tid & 15, row4 = tid >> 4;
#pragma unroll
    for (int j = 0; j < 4; j++) {
        int row = row4 + 16 * j;
        long o = (long)(r0 + row) * C + c0 + f4 * 4;
        float4 v = *(const float4*)(src + o);
        t[row][f4 * 4] = v.x; t[row][f4 * 4 + 1] = v.y;
        t[row][f4 * 4 + 2] = v.z; t[row][f4 * 4 + 3] = v.w;
        float l0, l1, l2, l3;
        uint2 uh{pack2(v.x, v.y, l0, l1), pack2(v.z, v.w, l2, l3)};
        uint2 ul{pack2lo(l0, l1), pack2lo(l2, l3)};
        *(uint2*)(dh + o) = uh;
        *(uint2*)(dl + o) = ul;
    }
    __syncthreads();
    int rg = tid & 15, cl = tid >> 4;
#pragma unroll
    for (int p = 0; p < 4; p++) {
        int c = cl + 16 * p;
        float v0 = t[4 * rg][c], v1 = t[4 * rg + 1][c];
        float v2 = t[4 * rg + 2][c], v3 = t[4 * rg + 3][c];
        float l0, l1, l2, l3;
        uint2 uh{pack2(v0, v1, l0, l1), pack2(v2, v3, l2, l3)};
        uint2 ul{pack2lo(l0, l1), pack2lo(l2, l3)};
        long o = (long)(c0 + c) * R + r0 + 4 * rg;
        *(uint2*)(th + o) = uh;
        *(uint2*)(tl + o) = ul;
    }
}

// zq direct + zs (lam-scaled, transposed) + zv (transposed). 4096x512.
__global__ void convZ4(const float* __restrict__ zq, const float* __restrict__ zs,
                       const float* __restrict__ zv,
                       __nv_bfloat16* __restrict__ qh, __nv_bfloat16* __restrict__ ql,
                       __nv_bfloat16* __restrict__ sh, __nv_bfloat16* __restrict__ sl,
                       __nv_bfloat16* __restrict__ vh, __nv_bfloat16* __restrict__ vl) {
    __shared__ float ts[64][65], tv[64][65];
    const int R = 4096, C = 512;
    int c0 = blockIdx.x * 64, r0 = blockIdx.y * 64;
    int tid = threadIdx.x;
    int f4 = tid & 15, row4 = tid >> 4;
#pragma unroll
    for (int j = 0; j < 4; j++) {
        int row = row4 + 16 * j;
        int r = r0 + row;
        long o = (long)r * C + c0 + f4 * 4;
        float lam = g_lam[r];
        float4 q = *(const float4*)(zq + o);
        float l0, l1, l2, l3;
        uint2 uh{pack2(q.x, q.y, l0, l1), pack2(q.z, q.w, l2, l3)};
        uint2 ul{pack2lo(l0, l1), pack2lo(l2, l3)};
        *(uint2*)(qh + o) = uh;
        *(uint2*)(ql + o) = ul;
        float4 s = *(const float4*)(zs + o);
        ts[row][f4 * 4] = s.x * lam; ts[row][f4 * 4 + 1] = s.y * lam;
        ts[row][f4 * 4 + 2] = s.z * lam; ts[row][f4 * 4 + 3] = s.w * lam;
        float4 v = *(const float4*)(zv + o);
        tv[row][f4 * 4] = v.x; tv[row][f4 * 4 + 1] = v.y;
        tv[row][f4 * 4 + 2] = v.z; tv[row][f4 * 4 + 3] = v.w;
    }
    __syncthreads();
    int rg = tid & 15, cl = tid >> 4;
#pragma unroll
    for (int p = 0; p < 4; p++) {
        int c = cl + 16 * p;
        long o = (long)(c0 + c) * R + r0 + 4 * rg;
        float l0, l1, l2, l3;
        {
            float v0 = ts[4 * rg][c], v1 = ts[4 * rg + 1][c];
            float v2 = ts[4 * rg + 2][c], v3 = ts[4 * rg + 3][c];
            uint2 uh{pack2(v0, v1, l0, l1), pack2(v2, v3, l2, l3)};
            uint2 ul{pack2lo(l0, l1), pack2lo(l2, l3)};
            *(uint2*)(sh + o) = uh;
            *(uint2*)(sl + o) = ul;
        }
        {
            float v0 = tv[4 * rg][c], v1 = tv[4 * rg + 1][c];
            float v2 = tv[4 * rg + 2][c], v3 = tv[4 * rg + 3][c];
            uint2 uh{pack2(v0, v1, l0, l1), pack2(v2, v3, l2, l3)};
            uint2 ul{pack2lo(l0, l1), pack2lo(l2, l3)};
            *(uint2*)(vh + o) = uh;
            *(uint2*)(vl + o) = ul;
        }
    }
}

// ---------------------------------------------------------------------------
// Dual-op HMMA bf16-split GEMM: one launch runs TWO independent GEMMs.
// Per 64-K-chunk: load Ah/Al/Bh/Bl once, issue hh+hl+lh MMA combos.
// 128x128 tile, 8 warps (4x2), warp tile 32x64, 2-stage cp.async pipeline.
// epi 0: C = alpha*acc;  epi 1: (Chi,Clo)=bf16-split(acc);
// epi 2: C = addC + acc/(g_cnt+1e-6)
// ---------------------------------------------------------------------------
static constexpr int ROWB = 144;
static constexpr int TILEB = 128 * ROWB;
static constexpr int BUFB = 4 * TILEB;
static constexpr int GSMEM = 2 * BUFB;   // 147456

struct GOp {
    const __nv_bfloat16 *Ah, *Al, *Bh, *Bl;
    float* C;
    __nv_bfloat16 *Chi, *Clo;
    const float* addC;
    int K, ldA, ldB, ldC, ksplit, epi, gx, gy, ctaCount;
    long sA, sB, sC, sAdd, sSplit;
    float alpha;
};

__global__ __launch_bounds__(256) void mma_dual(GOp op0, GOp op1) {
    extern __shared__ __align__(16) char sm[];
    const uint32_t sbase = smem_u32(sm);
    const int tid = threadIdx.x;
    const int wid = tid >> 5, lane = tid & 31;
    const int warpM = wid & 3, warpN = wid >> 2;

    const bool second = (int)blockIdx.x >= op0.ctaCount;
    const GOp op = second ? op1 : op0;
    int idx = (int)blockIdx.x - (second ? op0.ctaCount : 0);
    const int x = idx % op.gx;
    int rem = idx / op.gx;
    const int y = rem % op.gy;
    const int bz = rem / op.gy;
    const int batch = bz / op.ksplit;
    const int split = bz - batch * op.ksplit;

    const __nv_bfloat16* Ah = op.Ah + (long)batch * op.sA;
    const __nv_bfloat16* Al = op.Al + (long)batch * op.sA;
    const __nv_bfloat16* Bh = op.Bh + (long)batch * op.sB;
    const __nv_bfloat16* Bl = op.Bl + (long)batch * op.sB;
    const int kLen = op.K / op.ksplit;
    const long k0 = (long)split * kLen;
    const int rowA = y * 128;
    const int colB = x * 128;
    const int ldA = op.ldA, ldB = op.ldB, ldC = op.ldC;

    const int nCk = kLen >> 6;
    const int lr = tid >> 3;
    const int lc = tid & 7;

    float acc[2][8][4] = {};

    const uint32_t aAddrOff =
        (uint32_t)(warpM * 32 + (lane & 15)) * ROWB + (lane >> 4) * 16;
    const uint32_t bAddrOff =
        (uint32_t)(warpN * 64 + ((lane >> 4) << 3) + (lane & 7)) * ROWB +
        ((lane >> 3) & 1) * 16;

    auto issue_load = [&](int ck, int buf) {
        const long kb = k0 + (long)ck * 64;
        uint32_t base = sbase + buf * BUFB;
#pragma unroll
        for (int i = 0; i < 4; i++) {
            int r = lr + i * 32;
            uint32_t so = (uint32_t)r * ROWB + lc * 16;
            long ao = (long)(rowA + r) * ldA + kb + lc * 8;
            long bo = (long)(colB + r) * ldB + kb + lc * 8;
            cp16(base + so, Ah + ao);
            cp16(base + TILEB + so, Al + ao);
            cp16(base + 2 * TILEB + so, Bh + bo);
            cp16(base + 3 * TILEB + so, Bl + bo);
        }
    };

    issue_load(0, 0);
    cp_commit();

    for (int c = 0; c < nCk; c++) {
        const int buf = c & 1;
        if (c + 1 < nCk) {
            issue_load(c + 1, (c + 1) & 1);
            cp_commit();
            cp_wait1();
        } else {
            cp_wait0();
        }
        __syncthreads();

        uint32_t aH = sbase + buf * BUFB;
        uint32_t aL = aH + TILEB;
        uint32_t bH = aL + TILEB;
        uint32_t bL = bH + TILEB;
#pragma unroll
        for (int ks = 0; ks < 4; ks++) {
            uint32_t afh[2][4], afl[2][4];
#pragma unroll
            for (int mt = 0; mt < 2; mt++) {
                ldsm4(afh[mt], aH + aAddrOff + mt * (16 * ROWB) + ks * 32);
                ldsm4(afl[mt], aL + aAddrOff + mt * (16 * ROWB) + ks * 32);
            }
            uint32_t bfh[8][2], bfl[8][2];
#pragma unroll
            for (int q = 0; q < 4; q++) {
                uint32_t r4[4];
                ldsm4(r4, bH + bAddrOff + q * (16 * ROWB) + ks * 32);
                bfh[2 * q][0] = r4[0]; bfh[2 * q][1] = r4[1];
                bfh[2 * q + 1][0] = r4[2]; bfh[2 * q + 1][1] = r4[3];
                ldsm4(r4, bL + bAddrOff + q * (16 * ROWB) + ks * 32);
                bfl[2 * q][0] = r4[0]; bfl[2 * q][1] = r4[1];
                bfl[2 * q + 1][0] = r4[2]; bfl[2 * q + 1][1] = r4[3];
            }
#pragma unroll
            for (int mt = 0; mt < 2; mt++)
#pragma unroll
                for (int nt = 0; nt < 8; nt++) {
                    mma16816(acc[mt][nt], afh[mt], bfh[nt]);
                    mma16816(acc[mt][nt], afh[mt], bfl[nt]);
                    mma16816(acc[mt][nt], afl[mt], bfh[nt]);
                }
        }
        __syncthreads();
    }

    // epilogue (uniform per CTA)
    const int epi = op.epi;
    float scale = (epi == 2) ? (1.f / (g_cnt + 1e-6f)) : op.alpha;
    float* C = op.C;
    __nv_bfloat16* Chi = op.Chi;
    __nv_bfloat16* Clo = op.Clo;
    const float* addP = op.addC;
    if (epi == 1) { Chi += (long)batch * op.sC; Clo += (long)batch * op.sC; }
    else C += (long)batch * op.sC + (long)split * op.sSplit;
    if (epi == 2) addP += (long)batch * op.sAdd;

#pragma unroll
    for (int mt = 0; mt < 2; mt++) {
        int mrow = rowA + warpM * 32 + mt * 16 + (lane >> 2);
#pragma unroll
        for (int nt = 0; nt < 8; nt++) {
            int ncol = colB + warpN * 64 + nt * 8 + 2 * (lane & 3);
            long i0 = (long)mrow * ldC + ncol;
            long i1 = (long)(mrow + 8) * ldC + ncol;
            float2 v0{acc[mt][nt][0] * scale, acc[mt][nt][1] * scale};
            float2 v1{acc[mt][nt][2] * scale, acc[mt][nt][3] * scale};
            if (epi == 1) {
                __nv_bfloat16 h0, l0, h1, l1;
                split1(v0.x, h0, l0); split1(v0.y, h1, l1);
                *(__nv_bfloat162*)(Chi + i0) = __nv_bfloat162{h0, h1};
                *(__nv_bfloat162*)(Clo + i0) = __nv_bfloat162{l0, l1};
                split1(v1.x, h0, l0); split1(v1.y, h1, l1);
                *(__nv_bfloat162*)(Chi + i1) = __nv_bfloat162{h0, h1};
                *(__nv_bfloat162*)(Clo + i1) = __nv_bfloat162{l0, l1};
            } else {
                if (epi == 2) {
                    v0.x += addP[i0]; v0.y += addP[i0 + 1];
                    v1.x += addP[i1]; v1.y += addP[i1 + 1];
                }
                *(float2*)(C + i0) = v0;
                *(float2*)(C + i1) = v1;
            }
        }
    }
}

// ---------------------------------------------------------------------------
extern "C" void kernel_launch(void* const* d_in, const int* in_sizes, int n_in,
                              void* d_out, int out_size) {
    const float* zq = (const float*)d_in[0];
    const float* zs = (const float*)d_in[1];
    const float* zv = (const float*)d_in[2];
    const float* cf = (const float*)d_in[3];
    const float* Wk = (const float*)d_in[4];
    const float* Wv = (const float*)d_in[5];
    const float* Wo = (const float*)d_in[6];
    const float* mem = (const float*)d_in[7];

    float* out = (float*)d_out;
    float* vret = out;
    float* newmem = out + (long)Bn * Dn;

    float* pT;
    cudaGetSymbolAddress((void**)&pT, g_T);

#define SYM(p, s) __nv_bfloat16* p; cudaGetSymbolAddress((void**)&p, s)
    SYM(pWk_h, sWk_h);   SYM(pWk_l, sWk_l);
    SYM(pWkT_h, sWkT_h); SYM(pWkT_l, sWkT_l);
    SYM(pMemT_h, sMemT_h); SYM(pMemT_l, sMemT_l);
    SYM(pWvT_h, sWvT_h); SYM(pWvT_l, sWvT_l);
    SYM(pWoT_h, sWoT_h); SYM(pWoT_l, sWoT_l);
    SYM(pZq_h, sZq_h);   SYM(pZq_l, sZq_l);
    SYM(pZsT_h, sZsT_h); SYM(pZsT_l, sZsT_l);
    SYM(pZvT_h, sZvT_h); SYM(pZvT_l, sZvT_l);
    SYM(pA1_h, sA1_h);   SYM(pA1_l, sA1_l);
    SYM(pA2T_h, sA2T_h); SYM(pA2T_l, sA2T_l);
    SYM(pST_h, sST_h);   SYM(pST_l, sST_l);
    SYM(pT_h, sT_h);     SYM(pT_l, sT_l);
#undef SYM

    cudaFuncSetAttribute(mma_dual, cudaFuncAttributeMaxDynamicSharedMemorySize, GSMEM);

    prep_lam_kernel<<<1, 256>>>(cf);

    // conversions (vectorized)
    convWk4<<<dim3(128, 8), 256>>>(Wk, pWk_h, pWk_l, pWkT_h, pWkT_l);
    transSplit4<<<dim3(8, 128), 256>>>(mem, pMemT_h, pMemT_l, 8192, 512);
    transSplit4<<<dim3(128, 8), 256>>>(Wv, pWvT_h, pWvT_l, 512, 8192);
    transSplit4<<<dim3(8, 8), 256>>>(Wo, pWoT_h, pWoT_l, 512, 512);
    convZ4<<<dim3(8, 64), 256>>>(zq, zs, zv, pZq_h, pZq_l, pZsT_h, pZsT_l, pZvT_h, pZvT_l);

    auto mkop = [](const __nv_bfloat16* Ah, const __nv_bfloat16* Al,
                   const __nv_bfloat16* Bh, const __nv_bfloat16* Bl,
                   float* C, __nv_bfloat16* Chi, __nv_bfloat16* Clo, const float* addC,
                   int K, int ldA, int ldB, int ldC, int ksplit, int epi,
                   int gx, int gy, int gz, long sA, long sB, long sC, long sAdd,
                   long sSplit, float alpha) {
        GOp o;
        o.Ah = Ah; o.Al = Al; o.Bh = Bh; o.Bl = Bl;
        o.C = C; o.Chi = Chi; o.Clo = Clo; o.addC = addC;
        o.K = K; o.ldA = ldA; o.ldB = ldB; o.ldC = ldC;
        o.ksplit = ksplit; o.epi = epi; o.gx = gx; o.gy = gy;
        o.ctaCount = gx * gy * gz;
        o.sA = sA; o.sB = sB; o.sC = sC; o.sAdd = sAdd; o.sSplit = sSplit;
        o.alpha = alpha;
        return o;
    };

    // s1: A1 partials = Wk @ memT (K=8192, ksplit 8)  -> g_T[0..8DD)
    GOp s1 = mkop(pWk_h, pWk_l, pMemT_h, pMemT_l, pT, nullptr, nullptr, nullptr,
                  8192, 8192, 8192, 512, 8, 0, 4, 4, 8, 0, 0, 0, 0, DD, 1.f);
    // s4: S partials = zsT @ zvT (K=4096, ksplit 8)   -> g_T[8DD..16DD)
    GOp s4 = mkop(pZsT_h, pZsT_l, pZvT_h, pZvT_l, pT + 8 * DD, nullptr, nullptr, nullptr,
                  4096, 4096, 4096, 512, 8, 0, 4, 4, 8, 0, 0, 0, 0, DD, 1.f);
    mma_dual<<<s1.ctaCount + s4.ctaCount, 256, GSMEM>>>(s1, s4);

    reduce_split<<<(Dn * Dn + 255) / 256, 256>>>(pT, pA1_h, pA1_l, Dn * Dn, 8);
    reduce_splitT<<<dim3(16, 16), dim3(32, 8)>>>(pT + 8 * DD, pST_h, pST_l, 8);

    // s5: T_h = Wk_h^T @ S (16 heads, bf16 epilogue)
    GOp s5 = mkop(pWkT_h, pWkT_l, pST_h, pST_l, nullptr, pT_h, pT_l, nullptr,
                  512, 512, 512, 512, 1, 1, 4, 4, 16, DD, 0, DD, 0, 0, 1.f);
    // s2: A2 partials = (A1 @ Wo)/H (ksplit 4) -> g_T[0..4DD)
    GOp s2 = mkop(pA1_h, pA1_l, pWoT_h, pWoT_l, pT, nullptr, nullptr, nullptr,
                  512, 512, 512, 512, 4, 0, 4, 4, 4, 0, 0, 0, 0, DD, 1.f / Hn);
    mma_dual<<<s5.ctaCount + s2.ctaCount, 256, GSMEM>>>(s5, s2);

    reduce_splitT<<<dim3(16, 16), dim3(32, 8)>>>(pT, pA2T_h, pA2T_l, 4);

    // s6: new_mem_h = mem_h + (T_h @ Wv_h)/(cnt+1e-6)
    GOp s6 = mkop(pT_h, pT_l, pWvT_h, pWvT_l, newmem, nullptr, nullptr, mem,
                  512, 512, 512, 512, 1, 2, 4, 4, 16, DD, DD, DD, DD, 0, 1.f);
    // s3: v_ret = zq @ A2
    GOp s3 = mkop(pZq_h, pZq_l, pA2T_h, pA2T_l, vret, nullptr, nullptr, nullptr,
                  512, 512, 512, 512, 1, 0, 4, 32, 1, 0, 0, 0, 0, 0, 1.f);
    mma_dual<<<s6.ctaCount + s3.ctaCount, 256, GSMEM>>>(s6, s3);
}